// round 10
// baseline (speedup 1.0000x reference)
#include <cuda_runtime.h>
#include <cuda_bf16.h>
#include <math.h>

// ---------------------------------------------------------------------------
// Problem constants
// ---------------------------------------------------------------------------
#define Bsz   4
#define Dd    8
#define Ll    512
#define Hh    768
#define Ff    4096
#define NHEAD 8
#define HD    96         // head dim
#define TOPK  64
#define ROWS  16384      // B*D*L rows of H
#define NTOT  12582912LL // 16384*768
#define RES_ROWS 14336   // B*(D-1)*L
#define RES_TOT  11010048LL  // 14336*768
#define Z_TOT    58720256LL  // 14336*4096

#define O_LOSS  0LL
#define O_XHAT  1LL
#define O_NOVEL 11010049LL   // 1 + 11010048
#define O_Z     22020097LL   // 1 + 2*11010048

#define SQRT_HD 9.79795897113271239f   // fp32(sqrt(96)), == sqrtf(96.0f)

// ---------------------------------------------------------------------------
// Static device workspace (allocation-free rule: __device__ globals)
// ---------------------------------------------------------------------------
__device__ float g_ln  [NTOT];
__device__ float g_q   [NTOT];
__device__ float g_k   [NTOT];
__device__ float g_v   [NTOT];
__device__ float g_attn[NTOT];
__device__ float g_x   [NTOT];
__device__ float g_xt  [NTOT];
__device__ float g_sc  [67108864];    // 256 * 512 * 512 scores
__device__ float g_res [RES_TOT];
__device__ float g_z   [Z_TOT];
__device__ float g_dictT[Ff * Hh];
__device__ int   g_tki [RES_ROWS * TOPK];
__device__ float g_tkv [RES_ROWS * TOPK];
__device__ float g_part[3 * RES_ROWS]; // pred | recon | sparse partials

// ---------------------------------------------------------------------------
// LayerNorm: one block per row of 768, 256 threads. Two-pass variance
// (reference's literal mean(square(x - mu))), libdevice rsqrtf, IEEE
// divisions, NO fma contraction in the epilogue. BIT-PATH IS LOAD-BEARING.
// ---------------------------------------------------------------------------
__global__ void ln_kernel(const float* __restrict__ x, float* __restrict__ y,
                          const float* __restrict__ gg, const float* __restrict__ bb)
{
    long long row = blockIdx.x;
    const float* xr = x + row * Hh;
    float* yr = y + row * Hh;
    int t = threadIdx.x;
    float v0 = xr[t], v1 = xr[t + 256], v2 = xr[t + 512];
    __shared__ float sa[8], sq[8];

    float s = __fadd_rn(__fadd_rn(v0, v1), v2);
    #pragma unroll
    for (int o = 16; o; o >>= 1) s += __shfl_xor_sync(0xffffffffu, s, o);
    if ((t & 31) == 0) sa[t >> 5] = s;
    __syncthreads();
    s = 0.f;
    #pragma unroll
    for (int w = 0; w < 8; w++) s += sa[w];
    float mu = __fdiv_rn(s, 768.0f);

    float d0 = __fsub_rn(v0, mu), d1 = __fsub_rn(v1, mu), d2 = __fsub_rn(v2, mu);
    float s2 = __fadd_rn(__fadd_rn(__fmul_rn(d0, d0), __fmul_rn(d1, d1)), __fmul_rn(d2, d2));
    #pragma unroll
    for (int o = 16; o; o >>= 1) s2 += __shfl_xor_sync(0xffffffffu, s2, o);
    if ((t & 31) == 0) sq[t >> 5] = s2;
    __syncthreads();
    s2 = 0.f;
    #pragma unroll
    for (int w = 0; w < 8; w++) s2 += sq[w];
    float var  = __fdiv_rn(s2, 768.0f);
    float rstd = rsqrtf(__fadd_rn(var, 1e-5f));

    yr[t]       = __fadd_rn(__fmul_rn(__fmul_rn(d0, rstd), gg[t]),       bb[t]);
    yr[t + 256] = __fadd_rn(__fmul_rn(__fmul_rn(d1, rstd), gg[t + 256]), bb[t + 256]);
    yr[t + 512] = __fadd_rn(__fmul_rn(__fmul_rn(d2, rstd), gg[t + 512]), bb[t + 512]);
}

// ---------------------------------------------------------------------------
// Tiled SGEMM, STRICT k-ascending fp32 FMA accumulation per output element.
// The per-element rounding chain is identical to the R9 kernel (and thus
// correlated with the reference GEMM) — re-tiling only changes scheduling.
// DO NOT alter the accumulation order.
//
// BM=128, BN=128, BK=8, 256 threads, 8x8 register tile, double-buffered
// smem with register prefetch. smem-cycles : fma-cycles = 1:1 (was 1.5:1
// with the old 8x4 tile — ncu showed l1tex=76.7% as the roof).
//   TRANSB=true : C[M,N] = A[M,K] * B[N,K]^T
//   TRANSB=false: C[M,N] = A[M,K] * B[K,N]
// Requires M % 128 == 0, K % 8 == 0; N guarded at float4 grain.
// ---------------------------------------------------------------------------
template<bool TRANSB>
__global__ void __launch_bounds__(256, 2)
sgemm_kernel(const float* __restrict__ Ag, const float* __restrict__ Bg,
             float* __restrict__ Cg,
             const float* __restrict__ addsrc, const float* __restrict__ bias,
             int M, int N, int K, int lda, int ldb, int ldc,
             long long sA1, long long sA2, long long sB1, long long sB2,
             long long sC1, long long sC2, int bdiv,
             int relu)
{
    int z  = blockIdx.z;
    int z1 = z / bdiv, z2 = z - z1 * bdiv;
    const float* A = Ag + z1 * sA1 + z2 * sA2;
    const float* B = Bg + z1 * sB1 + z2 * sB2;
    float*       C = Cg + z1 * sC1 + z2 * sC2;
    const float* add = addsrc ? (addsrc + z1 * sC1 + z2 * sC2) : (const float*)0;

    __shared__ float As[2][8][128];
    __shared__ float Bs[2][8][128];

    int m0 = blockIdx.y * 128;
    int n0 = blockIdx.x * 128;
    int t  = threadIdx.x;
    int tx = t & 15, ty = t >> 4;

    // ---- load helpers (each thread: 1 float4 of A, 1 float4 of B) ----
    int ar  = t >> 1, akq = t & 1;          // A: row 0..127, k-quad 0..1
    const float* Aptr = A + (long long)(m0 + ar) * lda + akq * 4;

    int br, bkq, brk, bnq;
    const float* Bptr;
    if (TRANSB) {
        br = t >> 1; bkq = t & 1;           // B row (=n) 0..127, k-quad 0..1
        Bptr = B + (long long)(n0 + br) * ldb + bkq * 4;
    } else {
        brk = t >> 5; bnq = t & 31;         // B row (=k) 0..7, n-quad 0..31
        Bptr = B + (long long)brk * ldb + (n0 + bnq * 4);
    }
    bool bok;
    if (TRANSB) bok = (n0 + br  < N);
    else        bok = (n0 + bnq * 4 < N);

    float acc[8][8];
    #pragma unroll
    for (int i = 0; i < 8; i++)
        #pragma unroll
        for (int j = 0; j < 8; j++) acc[i][j] = 0.f;

    // ---- prologue: tile 0 into buffer 0 ----
    {
        float4 a4 = *(const float4*)(Aptr);
        As[0][akq*4+0][ar] = a4.x; As[0][akq*4+1][ar] = a4.y;
        As[0][akq*4+2][ar] = a4.z; As[0][akq*4+3][ar] = a4.w;
        float4 b4 = make_float4(0.f, 0.f, 0.f, 0.f);
        if (bok) b4 = *(const float4*)(Bptr);
        if (TRANSB) {
            Bs[0][bkq*4+0][br] = b4.x; Bs[0][bkq*4+1][br] = b4.y;
            Bs[0][bkq*4+2][br] = b4.z; Bs[0][bkq*4+3][br] = b4.w;
        } else {
            *(float4*)&Bs[0][brk][bnq * 4] = b4;
        }
    }
    __syncthreads();

    int buf = 0;
    for (int k0 = 0; k0 < K; k0 += 8) {
        // prefetch next tile into registers
        float4 a4n = make_float4(0.f,0.f,0.f,0.f), b4n = make_float4(0.f,0.f,0.f,0.f);
        bool have_next = (k0 + 8 < K);
        if (have_next) {
            a4n = *(const float4*)(Aptr + (k0 + 8));
            if (TRANSB) { if (bok) b4n = *(const float4*)(Bptr + (k0 + 8)); }
            else        { if (bok) b4n = *(const float4*)(Bptr + (long long)(k0 + 8) * ldb); }
        }

        // compute on current buffer (k strictly ascending)
        #pragma unroll
        for (int k = 0; k < 8; k++) {
            float a[8], b[8];
            *(float4*)&a[0] = *(const float4*)&As[buf][k][ty * 8];
            *(float4*)&a[4] = *(const float4*)&As[buf][k][ty * 8 + 4];
            *(float4*)&b[0] = *(const float4*)&Bs[buf][k][tx * 8];
            *(float4*)&b[4] = *(const float4*)&Bs[buf][k][tx * 8 + 4];
            #pragma unroll
            for (int i = 0; i < 8; i++)
                #pragma unroll
                for (int j = 0; j < 8; j++)
                    acc[i][j] += a[i] * b[j];   // FFMA, strict k order
        }

        // store prefetched tile into alternate buffer
        if (have_next) {
            int nb = buf ^ 1;
            As[nb][akq*4+0][ar] = a4n.x; As[nb][akq*4+1][ar] = a4n.y;
            As[nb][akq*4+2][ar] = a4n.z; As[nb][akq*4+3][ar] = a4n.w;
            if (TRANSB) {
                Bs[nb][bkq*4+0][br] = b4n.x; Bs[nb][bkq*4+1][br] = b4n.y;
                Bs[nb][bkq*4+2][br] = b4n.z; Bs[nb][bkq*4+3][br] = b4n.w;
            } else {
                *(float4*)&Bs[nb][brk][bnq * 4] = b4n;
            }
        }
        __syncthreads();
        buf ^= 1;
    }

    // ---- epilogue: 8 rows x 2 float4 per thread, N-guarded per quad ----
    #pragma unroll
    for (int i = 0; i < 8; i++) {
        long long m = m0 + ty * 8 + i;
        #pragma unroll
        for (int q = 0; q < 2; q++) {
            int n = n0 + tx * 8 + q * 4;
            if (n < N) {
                float4 r;
                r.x = acc[i][q*4+0]; r.y = acc[i][q*4+1];
                r.z = acc[i][q*4+2]; r.w = acc[i][q*4+3];
                if (bias) {
                    r.x = __fadd_rn(r.x, bias[n]);   r.y = __fadd_rn(r.y, bias[n+1]);
                    r.z = __fadd_rn(r.z, bias[n+2]); r.w = __fadd_rn(r.w, bias[n+3]);
                }
                if (add) {
                    float4 a4 = *(const float4*)(add + m * ldc + n);
                    r.x = __fadd_rn(r.x, a4.x); r.y = __fadd_rn(r.y, a4.y);
                    r.z = __fadd_rn(r.z, a4.z); r.w = __fadd_rn(r.w, a4.w);
                }
                if (relu) {
                    r.x = fmaxf(r.x, 0.f); r.y = fmaxf(r.y, 0.f);
                    r.z = fmaxf(r.z, 0.f); r.w = fmaxf(r.w, 0.f);
                }
                *(float4*)(C + m * ldc + n) = r;
            }
        }
    }
}

// ---------------------------------------------------------------------------
// Row softmax over 512 (non-causal), in place. One block (128 thr) per row.
// IEEE div by sqrt(96), libdevice expf, IEEE normalize. BIT-PATH LOAD-BEARING.
// ---------------------------------------------------------------------------
__global__ void softmax512_kernel(float* __restrict__ sc)
{
    long long row = blockIdx.x;
    float* p = sc + row * 512;
    int t = threadIdx.x;
    float v[4];
    #pragma unroll
    for (int i = 0; i < 4; i++) v[i] = __fdiv_rn(p[t + i * 128], SQRT_HD);
    float m = fmaxf(fmaxf(v[0], v[1]), fmaxf(v[2], v[3]));
    __shared__ float sm[4], ss[4];
    #pragma unroll
    for (int o = 16; o; o >>= 1) m = fmaxf(m, __shfl_xor_sync(0xffffffffu, m, o));
    if ((t & 31) == 0) sm[t >> 5] = m;
    __syncthreads();
    m = fmaxf(fmaxf(sm[0], sm[1]), fmaxf(sm[2], sm[3]));
    float s = 0.f;
    #pragma unroll
    for (int i = 0; i < 4; i++) { v[i] = expf(__fsub_rn(v[i], m)); s += v[i]; }
    #pragma unroll
    for (int o = 16; o; o >>= 1) s += __shfl_xor_sync(0xffffffffu, s, o);
    if ((t & 31) == 0) ss[t >> 5] = s;
    __syncthreads();
    s = ss[0] + ss[1] + ss[2] + ss[3];
    #pragma unroll
    for (int i = 0; i < 4; i++) p[t + i * 128] = __fdiv_rn(v[i], s);
}

// ---------------------------------------------------------------------------
// Tiny causal attention over depth (D=8 tokens). Block = (bl, head), 128 thr.
// ---------------------------------------------------------------------------
__global__ void attn2_kernel(const float* __restrict__ q, const float* __restrict__ k,
                             const float* __restrict__ v, float* __restrict__ o)
{
    int bl = blockIdx.x;   // 0..2047 = b*512+l
    int h  = blockIdx.y;   // 0..7
    int t  = threadIdx.x;  // 128
    __shared__ float qs[8][97], ks[8][97], vs[8][97], ps[8][8];
    long long base = (long long)bl * 8 * Hh + h * HD;
    if (t < 96) {
        #pragma unroll
        for (int tok = 0; tok < 8; tok++) {
            qs[tok][t] = q[base + tok * Hh + t];
            ks[tok][t] = k[base + tok * Hh + t];
            vs[tok][t] = v[base + tok * Hh + t];
        }
    }
    __syncthreads();
    if (t < 64) {
        int t1 = t >> 3, t2 = t & 7;
        float s = -1e30f;
        if (t2 <= t1) {
            float a = 0.f;
            #pragma unroll 8
            for (int d2 = 0; d2 < 96; d2++) a += qs[t1][d2] * ks[t2][d2];  // FFMA, d ascending
            s = __fdiv_rn(a, SQRT_HD);
        }
        float m = s;
        #pragma unroll
        for (int o2 = 1; o2 <= 4; o2 <<= 1) m = fmaxf(m, __shfl_xor_sync(0xffffffffu, m, o2));
        float e = (t2 <= t1) ? expf(__fsub_rn(s, m)) : 0.0f;
        float sum = e;
        #pragma unroll
        for (int o2 = 1; o2 <= 4; o2 <<= 1) sum += __shfl_xor_sync(0xffffffffu, sum, o2);
        ps[t1][t2] = __fdiv_rn(e, sum);
    }
    __syncthreads();
    if (t < 96) {
        #pragma unroll
        for (int t1 = 0; t1 < 8; t1++) {
            float a = 0.f;
            #pragma unroll
            for (int t2 = 0; t2 < 8; t2++) a += ps[t1][t2] * vs[t2][t];    // FFMA, m ascending
            o[base + t1 * Hh + t] = a;
        }
    }
}

// ---------------------------------------------------------------------------
// Layout permutes: (B,D,L,H) <-> (B,L,D,H)
// ---------------------------------------------------------------------------
__global__ void perm_fwd_kernel(const float* __restrict__ in, float* __restrict__ out)
{
    long long i = (long long)blockIdx.x * 256 + threadIdx.x;
    if (i >= NTOT) return;
    int h = (int)(i % Hh);
    long long r = i / Hh;
    int l = (int)(r % Ll);
    long long bd = r / Ll;
    int dd = (int)(bd % Dd);
    int b  = (int)(bd / Dd);
    out[((long long)(b * Ll + l) * Dd + dd) * Hh + h] = in[i];
}

__global__ void perm_bwd_kernel(const float* __restrict__ in, float* __restrict__ out)
{
    long long i = (long long)blockIdx.x * 256 + threadIdx.x;
    if (i >= NTOT) return;
    int h = (int)(i % Hh);
    long long r = i / Hh;
    int l = (int)(r % Ll);
    long long bd = r / Ll;
    int dd = (int)(bd % Dd);
    int b  = (int)(bd / Dd);
    out[i] = in[((long long)(b * Ll + l) * Dd + dd) * Hh + h];
}

// ---------------------------------------------------------------------------
// Dictionary transpose: (768,4096) -> (4096,768)
// ---------------------------------------------------------------------------
__global__ void transpose_dict_kernel(const float* __restrict__ in, float* __restrict__ out)
{
    __shared__ float tile[32][33];
    int bx = blockIdx.x * 32;   // F dir
    int by = blockIdx.y * 32;   // H dir
    int x = threadIdx.x, y = threadIdx.y;
    #pragma unroll
    for (int j = 0; j < 32; j += 8)
        tile[y + j][x] = in[(long long)(by + y + j) * Ff + bx + x];
    __syncthreads();
    #pragma unroll
    for (int j = 0; j < 32; j += 8)
        out[(long long)(bx + y + j) * Hh + by + x] = tile[x][y + j];
}

// ---------------------------------------------------------------------------
// residual = x[:,1:] - x[:,:-1]  (row-major (B,7,L,H))
// ---------------------------------------------------------------------------
__global__ void res_kernel(const float* __restrict__ x, float* __restrict__ res)
{
    long long i = (long long)blockIdx.x * 256 + threadIdx.x;
    if (i >= RES_TOT) return;
    int h = (int)(i % Hh);
    long long r = i / Hh;
    int l = (int)(r % Ll);
    long long bd = r / Ll;
    int dd = (int)(bd % 7);
    int b  = (int)(bd / 7);
    long long i0 = ((long long)(b * Dd + dd) * Ll + l) * Hh + h;
    res[i] = __fsub_rn(x[i0 + (long long)Ll * Hh], x[i0]);
}

// ---------------------------------------------------------------------------
// Top-64 per row of 4096 (iterative argmax; values relu'd >= 0, ties broken
// by lowest index, matching jax.lax.top_k). Writes z_n directly into d_out,
// records (idx,val) pairs and per-row L1 sum.
// ---------------------------------------------------------------------------
__global__ void topk_kernel(const float* __restrict__ z, float* __restrict__ out,
                            int* __restrict__ tki, float* __restrict__ tkv,
                            float* __restrict__ sparse_part)
{
    long long row = blockIdx.x;
    const float* zr = z + row * Ff;
    __shared__ float rS[Ff];
    __shared__ float wS[Ff];
    __shared__ float bmv[8];
    __shared__ int   bmi[8];
    int t = threadIdx.x;
    for (int i = t; i < Ff; i += 256) { float vv = zr[i]; rS[i] = vv; wS[i] = vv; }
    __syncthreads();

    for (int it = 0; it < TOPK; it++) {
        float bv = -1.0f; int bi = 0x7fffffff;
        for (int i = t; i < Ff; i += 256) {
            float vv = wS[i];
            if (vv > bv || (vv == bv && i < bi)) { bv = vv; bi = i; }
        }
        #pragma unroll
        for (int o = 16; o; o >>= 1) {
            float ov = __shfl_down_sync(0xffffffffu, bv, o);
            int   oi = __shfl_down_sync(0xffffffffu, bi, o);
            if (ov > bv || (ov == bv && oi < bi)) { bv = ov; bi = oi; }
        }
        if ((t & 31) == 0) { bmv[t >> 5] = bv; bmi[t >> 5] = bi; }
        __syncthreads();
        if (t == 0) {
            #pragma unroll
            for (int w = 1; w < 8; w++) {
                if (bmv[w] > bv || (bmv[w] == bv && bmi[w] < bi)) { bv = bmv[w]; bi = bmi[w]; }
            }
            wS[bi] = -1.0f;                 // mark selected
            tki[row * TOPK + it] = bi;
            tkv[row * TOPK + it] = bv;
        }
        __syncthreads();
    }

    // emit full row (selected value or 0) + per-row L1 partial
    float ls = 0.f;
    long long ob = O_Z + row * Ff;
    for (int i = t; i < Ff; i += 256) {
        float vv = (wS[i] < 0.0f) ? rS[i] : 0.0f;
        out[ob + i] = vv;
        ls += vv;
    }
    __shared__ float sp[8];
    #pragma unroll
    for (int o = 16; o; o >>= 1) ls += __shfl_xor_sync(0xffffffffu, ls, o);
    if ((t & 31) == 0) sp[t >> 5] = ls;
    __syncthreads();
    if (t == 0) {
        float s = 0.f;
        #pragma unroll
        for (int w = 0; w < 8; w++) s += sp[w];
        sparse_part[row] = s;
    }
}

// ---------------------------------------------------------------------------
// Sparse decode: x_novel = sum_j z_j * dictT[j], fused with x_hat and
// per-row pred/recon loss partials. Block per row (256 threads, 3 dims each).
// ---------------------------------------------------------------------------
__global__ void novel_kernel(const float* __restrict__ dictT, const float* __restrict__ x,
                             const int* __restrict__ tki, const float* __restrict__ tkv,
                             float* __restrict__ out,
                             float* __restrict__ pred_part, float* __restrict__ recon_part)
{
    long long row = blockIdx.x;     // (b*7+dd)*512 + l
    int t = threadIdx.x;
    __shared__ int   sI[TOPK];
    __shared__ float sV[TOPK];
    if (t < TOPK) { sI[t] = tki[row * TOPK + t]; sV[t] = tkv[row * TOPK + t]; }
    __syncthreads();

    int l = (int)(row % Ll);
    long long bd = row / Ll;
    int dd = (int)(bd % 7);
    int b  = (int)(bd / 7);
    const float* xp = x + ((long long)(b * Dd + dd)     * Ll + l) * Hh;
    const float* xt = x + ((long long)(b * Dd + dd + 1) * Ll + l) * Hh;

    float a0 = 0.f, a1 = 0.f, a2 = 0.f;
    #pragma unroll 4
    for (int j = 0; j < TOPK; j++) {
        float vv = sV[j];
        const float* dr = dictT + (long long)sI[j] * Hh;
        a0 += vv * dr[t];
        a1 += vv * dr[t + 256];
        a2 += vv * dr[t + 512];
    }

    float lr = 0.f, lp = 0.f;
    long long ob = row * Hh;
    float nv[3] = { a0, a1, a2 };
    #pragma unroll
    for (int i = 0; i < 3; i++) {
        int h = t + i * 256;
        float px = xp[h], tg = xt[h];
        float nov = nv[i];
        float xh = __fadd_rn(px, nov);
        out[O_NOVEL + ob + h] = nov;
        out[O_XHAT  + ob + h] = xh;
        float d1 = __fsub_rn(xh, tg); lr += d1 * d1;
        float d2 = __fsub_rn(tg, px); lp += d2 * d2;
    }
    __shared__ float s1[8], s2[8];
    #pragma unroll
    for (int o = 16; o; o >>= 1) {
        lr += __shfl_xor_sync(0xffffffffu, lr, o);
        lp += __shfl_xor_sync(0xffffffffu, lp, o);
    }
    if ((t & 31) == 0) { s1[t >> 5] = lr; s2[t >> 5] = lp; }
    __syncthreads();
    if (t == 0) {
        float r = 0.f, p = 0.f;
        #pragma unroll
        for (int w = 0; w < 8; w++) { r += s1[w]; p += s2[w]; }
        recon_part[row] = r;
        pred_part[row]  = p;
    }
}

// ---------------------------------------------------------------------------
// Final deterministic loss reduction
// ---------------------------------------------------------------------------
__global__ void loss_kernel(const float* __restrict__ pred_part,
                            const float* __restrict__ recon_part,
                            const float* __restrict__ sparse_part,
                            float* __restrict__ out)
{
    int t = threadIdx.x;   // 256
    double sp = 0.0, sr = 0.0, ss = 0.0;
    for (int i = t; i < RES_ROWS; i += 256) {
        sp += (double)pred_part[i];
        sr += (double)recon_part[i];
        ss += (double)sparse_part[i];
    }
    __shared__ double da[256], db[256], dc[256];
    da[t] = sp; db[t] = sr; dc[t] = ss;
    __syncthreads();
    for (int o = 128; o; o >>= 1) {
        if (t < o) { da[t] += da[t + o]; db[t] += db[t + o]; dc[t] += dc[t + o]; }
        __syncthreads();
    }
    if (t == 0) {
        double loss = da[0] / 11010048.0 + db[0] / 11010048.0 + 0.001 * (dc[0] / 58720256.0);
        out[O_LOSS] = (float)loss;
    }
}

// ---------------------------------------------------------------------------
// Host side
// ---------------------------------------------------------------------------
static void sgemm(bool transB, const float* A, const float* B, float* C,
                  const float* add, const float* bias,
                  int M, int N, int K, int lda, int ldb, int ldc,
                  long long sA1, long long sA2, long long sB1, long long sB2,
                  long long sC1, long long sC2, int bdiv, int batch,
                  int relu)
{
    dim3 grid((N + 127) / 128, M / 128, batch);
    if (transB)
        sgemm_kernel<true><<<grid, 256>>>(A, B, C, add, bias, M, N, K, lda, ldb, ldc,
                                          sA1, sA2, sB1, sB2, sC1, sC2, bdiv, relu);
    else
        sgemm_kernel<false><<<grid, 256>>>(A, B, C, add, bias, M, N, K, lda, ldb, ldc,
                                           sA1, sA2, sB1, sB2, sC1, sC2, bdiv, relu);
}

extern "C" void kernel_launch(void* const* d_in, const int* in_sizes, int n_in,
                              void* d_out, int out_size)
{
    const float* zL    = (const float*)d_in[0];
    const float* Wq_l  = (const float*)d_in[1];
    const float* Wk_l  = (const float*)d_in[2];
    const float* Wv_l  = (const float*)d_in[3];
    const float* Wo_l  = (const float*)d_in[4];
    const float* gl    = (const float*)d_in[5];
    const float* bl    = (const float*)d_in[6];
    const float* Wq_d  = (const float*)d_in[7];
    const float* Wk_d  = (const float*)d_in[8];
    const float* Wv_d  = (const float*)d_in[9];
    const float* Wo_d  = (const float*)d_in[10];
    const float* gd    = (const float*)d_in[11];
    const float* bd    = (const float*)d_in[12];
    const float* dict  = (const float*)d_in[13];
    const float* biasn = (const float*)d_in[14];
    float* out = (float*)d_out;

    float *p_ln, *p_q, *p_k, *p_v, *p_attn, *p_x, *p_xt, *p_sc, *p_res, *p_z, *p_dT, *p_tkv, *p_part;
    int *p_tki;
    cudaGetSymbolAddress((void**)&p_ln,   g_ln);
    cudaGetSymbolAddress((void**)&p_q,    g_q);
    cudaGetSymbolAddress((void**)&p_k,    g_k);
    cudaGetSymbolAddress((void**)&p_v,    g_v);
    cudaGetSymbolAddress((void**)&p_attn, g_attn);
    cudaGetSymbolAddress((void**)&p_x,    g_x);
    cudaGetSymbolAddress((void**)&p_xt,   g_xt);
    cudaGetSymbolAddress((void**)&p_sc,   g_sc);
    cudaGetSymbolAddress((void**)&p_res,  g_res);
    cudaGetSymbolAddress((void**)&p_z,    g_z);
    cudaGetSymbolAddress((void**)&p_dT,   g_dictT);
    cudaGetSymbolAddress((void**)&p_tki,  g_tki);
    cudaGetSymbolAddress((void**)&p_tkv,  g_tkv);
    cudaGetSymbolAddress((void**)&p_part, g_part);

    const long long SQH = (long long)Ll * Hh;       // 512*768 seq stride
    const long long SCB = (long long)Ll * Ll;       // 512*512 per-head score size

    // ---------------- Stage A: attention over L (non-causal) ----------------
    ln_kernel<<<ROWS, 256>>>(zL, p_ln, gl, bl);
    sgemm(true, p_ln, Wq_l, p_q, 0, 0, ROWS, Hh, Hh, Hh, Hh, Hh, 0,0,0,0,0,0, 1, 1, 0);
    sgemm(true, p_ln, Wk_l, p_k, 0, 0, ROWS, Hh, Hh, Hh, Hh, Hh, 0,0,0,0,0,0, 1, 1, 0);
    sgemm(true, p_ln, Wv_l, p_v, 0, 0, ROWS, Hh, Hh, Hh, Hh, Hh, 0,0,0,0,0,0, 1, 1, 0);
    // raw scores[seq,head] = Q K^T (scaling done in softmax with IEEE div)
    sgemm(true, p_q, p_k, p_sc, 0, 0, Ll, Ll, HD, Hh, Hh, Ll,
          SQH, HD, SQH, HD, 8*SCB, SCB, NHEAD, 32*NHEAD, 0);
    softmax512_kernel<<<131072, 128>>>(p_sc);
    // attn = P V
    sgemm(false, p_sc, p_v, p_attn, 0, 0, Ll, HD, Ll, Ll, Hh, Hh,
          8*SCB, SCB, SQH, HD, SQH, HD, NHEAD, 32*NHEAD, 0);
    // x = zL + attn Wo^T
    sgemm(true, p_attn, Wo_l, p_x, zL, 0, ROWS, Hh, Hh, Hh, Hh, Hh, 0,0,0,0,0,0, 1, 1, 0);

    // ---------------- Stage B: causal attention over depth D ----------------
    perm_fwd_kernel<<<49152, 256>>>(p_x, p_xt);
    ln_kernel<<<ROWS, 256>>>(p_xt, p_ln, gd, bd);
    sgemm(true, p_ln, Wq_d, p_q, 0, 0, ROWS, Hh, Hh, Hh, Hh, Hh, 0,0,0,0,0,0, 1, 1, 0);
    sgemm(true, p_ln, Wk_d, p_k, 0, 0, ROWS, Hh, Hh, Hh, Hh, Hh, 0,0,0,0,0,0, 1, 1, 0);
    sgemm(true, p_ln, Wv_d, p_v, 0, 0, ROWS, Hh, Hh, Hh, Hh, Hh, 0,0,0,0,0,0, 1, 1, 0);
    attn2_kernel<<<dim3(2048, NHEAD), 128>>>(p_q, p_k, p_v, p_attn);
    sgemm(true, p_attn, Wo_d, p_xt, p_xt, 0, ROWS, Hh, Hh, Hh, Hh, Hh, 0,0,0,0,0,0, 1, 1, 0);
    perm_bwd_kernel<<<49152, 256>>>(p_xt, p_x);

    // ---------------- SAE head ----------------
    transpose_dict_kernel<<<dim3(128, 24), dim3(32, 8)>>>(dict, p_dT);
    res_kernel<<<43008, 256>>>(p_x, p_res);
    // z_dense = relu(res @ dict + bias)   (strict k-seq FMA -> correlates with ref)
    sgemm(false, p_res, dict, p_z, 0, biasn, RES_ROWS, Ff, Hh, Hh, Ff, Ff,
          0,0,0,0,0,0, 1, 1, 1);
    topk_kernel<<<RES_ROWS, 256>>>(p_z, out, p_tki, p_tkv, p_part + 2 * RES_ROWS);
    novel_kernel<<<RES_ROWS, 256>>>(p_dT, p_x, p_tki, p_tkv, out,
                                    p_part, p_part + RES_ROWS);
    loss_kernel<<<1, 256>>>(p_part, p_part + RES_ROWS, p_part + 2 * RES_ROWS, out);
}

// round 11
// speedup vs baseline: 1.0300x; 1.0300x over previous
#include <cuda_runtime.h>
#include <cuda_bf16.h>
#include <math.h>

// ---------------------------------------------------------------------------
// Problem constants
// ---------------------------------------------------------------------------
#define Bsz   4
#define Dd    8
#define Ll    512
#define Hh    768
#define Ff    4096
#define NHEAD 8
#define HD    96         // head dim
#define TOPK  64
#define ROWS  16384      // B*D*L rows of H
#define NTOT  12582912LL // 16384*768
#define RES_ROWS 14336   // B*(D-1)*L
#define RES_TOT  11010048LL  // 14336*768
#define Z_TOT    58720256LL  // 14336*4096

#define O_LOSS  0LL
#define O_XHAT  1LL
#define O_NOVEL 11010049LL   // 1 + 11010048
#define O_Z     22020097LL   // 1 + 2*11010048

#define SQRT_HD 9.79795897113271239f   // fp32(sqrt(96)), == sqrtf(96.0f)

// ---------------------------------------------------------------------------
// Static device workspace (allocation-free rule: __device__ globals)
// ---------------------------------------------------------------------------
__device__ float g_ln  [NTOT];
__device__ float g_q   [NTOT];
__device__ float g_k   [NTOT];
__device__ float g_v   [NTOT];
__device__ float g_attn[NTOT];
__device__ float g_x   [NTOT];
__device__ float g_xt  [NTOT];
__device__ float g_sc  [67108864];    // 256 * 512 * 512 scores
__device__ float g_res [RES_TOT];
__device__ float g_z   [Z_TOT];
__device__ float g_dictT[Ff * Hh];
__device__ int   g_tki [RES_ROWS * TOPK];
__device__ float g_tkv [RES_ROWS * TOPK];
__device__ float g_part[3 * RES_ROWS]; // pred | recon | sparse partials

// ---------------------------------------------------------------------------
// LayerNorm: one block per row of 768, 256 threads. Two-pass variance
// (reference's literal mean(square(x - mu))), libdevice rsqrtf, IEEE
// divisions, NO fma contraction in the epilogue. BIT-PATH IS LOAD-BEARING.
// ---------------------------------------------------------------------------
__global__ void ln_kernel(const float* __restrict__ x, float* __restrict__ y,
                          const float* __restrict__ gg, const float* __restrict__ bb)
{
    long long row = blockIdx.x;
    const float* xr = x + row * Hh;
    float* yr = y + row * Hh;
    int t = threadIdx.x;
    float v0 = xr[t], v1 = xr[t + 256], v2 = xr[t + 512];
    __shared__ float sa[8], sq[8];

    float s = __fadd_rn(__fadd_rn(v0, v1), v2);
    #pragma unroll
    for (int o = 16; o; o >>= 1) s += __shfl_xor_sync(0xffffffffu, s, o);
    if ((t & 31) == 0) sa[t >> 5] = s;
    __syncthreads();
    s = 0.f;
    #pragma unroll
    for (int w = 0; w < 8; w++) s += sa[w];
    float mu = __fdiv_rn(s, 768.0f);

    float d0 = __fsub_rn(v0, mu), d1 = __fsub_rn(v1, mu), d2 = __fsub_rn(v2, mu);
    float s2 = __fadd_rn(__fadd_rn(__fmul_rn(d0, d0), __fmul_rn(d1, d1)), __fmul_rn(d2, d2));
    #pragma unroll
    for (int o = 16; o; o >>= 1) s2 += __shfl_xor_sync(0xffffffffu, s2, o);
    if ((t & 31) == 0) sq[t >> 5] = s2;
    __syncthreads();
    s2 = 0.f;
    #pragma unroll
    for (int w = 0; w < 8; w++) s2 += sq[w];
    float var  = __fdiv_rn(s2, 768.0f);
    float rstd = rsqrtf(__fadd_rn(var, 1e-5f));

    yr[t]       = __fadd_rn(__fmul_rn(__fmul_rn(d0, rstd), gg[t]),       bb[t]);
    yr[t + 256] = __fadd_rn(__fmul_rn(__fmul_rn(d1, rstd), gg[t + 256]), bb[t + 256]);
    yr[t + 512] = __fadd_rn(__fmul_rn(__fmul_rn(d2, rstd), gg[t + 512]), bb[t + 512]);
}

// ---------------------------------------------------------------------------
// Tiled SGEMM, STRICT k-ascending fp32 FMA accumulation per output element.
// Per-element rounding chain is identical to R9 (correlated with the
// reference GEMM — protects the top-k boundary). DO NOT alter the order.
//
// R11 tile: BM=128, BN=64, BK=16, 128 threads, 8x8 register fragment,
// single-buffered smem. smem-bytes : fma ratio = 1:1 (R9's 8x4 was 1.5:1 and
// ncu showed l1tex=76.7% roof; R10's 256-thread/double-buffer variant hit
// the 128-reg ceiling and regressed). ~95 regs -> 4 CTAs/SM, 4 independent
// barriers to interleave sync stalls.
//   TRANSB=true : C[M,N] = A[M,K] * B[N,K]^T
//   TRANSB=false: C[M,N] = A[M,K] * B[K,N]
// Requires M % 128 == 0, K % 16 == 0; N guarded at float4 grain.
// ---------------------------------------------------------------------------
template<bool TRANSB>
__global__ void __launch_bounds__(128, 4)
sgemm_kernel(const float* __restrict__ Ag, const float* __restrict__ Bg,
             float* __restrict__ Cg,
             const float* __restrict__ addsrc, const float* __restrict__ bias,
             int M, int N, int K, int lda, int ldb, int ldc,
             long long sA1, long long sA2, long long sB1, long long sB2,
             long long sC1, long long sC2, int bdiv,
             int relu)
{
    int z  = blockIdx.z;
    int z1 = z / bdiv, z2 = z - z1 * bdiv;
    const float* A = Ag + z1 * sA1 + z2 * sA2;
    const float* B = Bg + z1 * sB1 + z2 * sB2;
    float*       C = Cg + z1 * sC1 + z2 * sC2;
    const float* add = addsrc ? (addsrc + z1 * sC1 + z2 * sC2) : (const float*)0;

    __shared__ float As[16][128];
    __shared__ float Bs[16][64];

    int m0 = blockIdx.y * 128;
    int n0 = blockIdx.x * 64;
    int t  = threadIdx.x;          // 128 threads
    int tx = t & 7, ty = t >> 3;   // 8 x 16 thread grid -> 64 x 128 coverage

    float acc[8][8];
    #pragma unroll
    for (int i = 0; i < 8; i++)
        #pragma unroll
        for (int j = 0; j < 8; j++) acc[i][j] = 0.f;

    for (int k0 = 0; k0 < K; k0 += 16) {
        // ---- A tile: 128 rows x 16 k = 512 float4, 4 per thread ----
        #pragma unroll
        for (int r = 0; r < 4; r++) {
            int i   = t + r * 128;
            int row = i >> 2, kq = i & 3;
            float4 a4 = *(const float4*)(A + (long long)(m0 + row) * lda + (k0 + kq * 4));
            As[kq*4+0][row] = a4.x;
            As[kq*4+1][row] = a4.y;
            As[kq*4+2][row] = a4.z;
            As[kq*4+3][row] = a4.w;
        }
        // ---- B tile: 256 float4, 2 per thread ----
        if (TRANSB) {
            #pragma unroll
            for (int r = 0; r < 2; r++) {
                int i  = t + r * 128;
                int n  = i >> 2, kq = i & 3;
                float4 b4 = make_float4(0.f, 0.f, 0.f, 0.f);
                if (n0 + n < N)
                    b4 = *(const float4*)(B + (long long)(n0 + n) * ldb + (k0 + kq * 4));
                Bs[kq*4+0][n] = b4.x;
                Bs[kq*4+1][n] = b4.y;
                Bs[kq*4+2][n] = b4.z;
                Bs[kq*4+3][n] = b4.w;
            }
        } else {
            #pragma unroll
            for (int r = 0; r < 2; r++) {
                int i  = t + r * 128;
                int rk = i >> 4, nq = i & 15;
                float4 b4 = make_float4(0.f, 0.f, 0.f, 0.f);
                if (n0 + nq * 4 < N)
                    b4 = *(const float4*)(B + (long long)(k0 + rk) * ldb + (n0 + nq * 4));
                *(float4*)&Bs[rk][nq * 4] = b4;
            }
        }
        __syncthreads();
        #pragma unroll
        for (int k = 0; k < 16; k++) {
            float a[8], b[8];
            *(float4*)&a[0] = *(const float4*)&As[k][ty * 8];
            *(float4*)&a[4] = *(const float4*)&As[k][ty * 8 + 4];
            *(float4*)&b[0] = *(const float4*)&Bs[k][tx * 8];
            *(float4*)&b[4] = *(const float4*)&Bs[k][tx * 8 + 4];
            #pragma unroll
            for (int i = 0; i < 8; i++)
                #pragma unroll
                for (int j = 0; j < 8; j++)
                    acc[i][j] += a[i] * b[j];   // FFMA, strict k order
        }
        __syncthreads();
    }

    // ---- epilogue: 8 rows x 2 float4 per thread, N-guarded per quad ----
    #pragma unroll
    for (int i = 0; i < 8; i++) {
        long long m = m0 + ty * 8 + i;
        #pragma unroll
        for (int q = 0; q < 2; q++) {
            int n = n0 + tx * 8 + q * 4;
            if (n < N) {
                float4 r;
                r.x = acc[i][q*4+0]; r.y = acc[i][q*4+1];
                r.z = acc[i][q*4+2]; r.w = acc[i][q*4+3];
                if (bias) {
                    r.x = __fadd_rn(r.x, bias[n]);   r.y = __fadd_rn(r.y, bias[n+1]);
                    r.z = __fadd_rn(r.z, bias[n+2]); r.w = __fadd_rn(r.w, bias[n+3]);
                }
                if (add) {
                    float4 a4 = *(const float4*)(add + m * ldc + n);
                    r.x = __fadd_rn(r.x, a4.x); r.y = __fadd_rn(r.y, a4.y);
                    r.z = __fadd_rn(r.z, a4.z); r.w = __fadd_rn(r.w, a4.w);
                }
                if (relu) {
                    r.x = fmaxf(r.x, 0.f); r.y = fmaxf(r.y, 0.f);
                    r.z = fmaxf(r.z, 0.f); r.w = fmaxf(r.w, 0.f);
                }
                *(float4*)(C + m * ldc + n) = r;
            }
        }
    }
}

// ---------------------------------------------------------------------------
// Row softmax over 512 (non-causal), in place. One block (128 thr) per row.
// IEEE div by sqrt(96), libdevice expf, IEEE normalize. BIT-PATH LOAD-BEARING.
// ---------------------------------------------------------------------------
__global__ void softmax512_kernel(float* __restrict__ sc)
{
    long long row = blockIdx.x;
    float* p = sc + row * 512;
    int t = threadIdx.x;
    float v[4];
    #pragma unroll
    for (int i = 0; i < 4; i++) v[i] = __fdiv_rn(p[t + i * 128], SQRT_HD);
    float m = fmaxf(fmaxf(v[0], v[1]), fmaxf(v[2], v[3]));
    __shared__ float sm[4], ss[4];
    #pragma unroll
    for (int o = 16; o; o >>= 1) m = fmaxf(m, __shfl_xor_sync(0xffffffffu, m, o));
    if ((t & 31) == 0) sm[t >> 5] = m;
    __syncthreads();
    m = fmaxf(fmaxf(sm[0], sm[1]), fmaxf(sm[2], sm[3]));
    float s = 0.f;
    #pragma unroll
    for (int i = 0; i < 4; i++) { v[i] = expf(__fsub_rn(v[i], m)); s += v[i]; }
    #pragma unroll
    for (int o = 16; o; o >>= 1) s += __shfl_xor_sync(0xffffffffu, s, o);
    if ((t & 31) == 0) ss[t >> 5] = s;
    __syncthreads();
    s = ss[0] + ss[1] + ss[2] + ss[3];
    #pragma unroll
    for (int i = 0; i < 4; i++) p[t + i * 128] = __fdiv_rn(v[i], s);
}

// ---------------------------------------------------------------------------
// Tiny causal attention over depth (D=8 tokens). Block = (bl, head), 128 thr.
// ---------------------------------------------------------------------------
__global__ void attn2_kernel(const float* __restrict__ q, const float* __restrict__ k,
                             const float* __restrict__ v, float* __restrict__ o)
{
    int bl = blockIdx.x;   // 0..2047 = b*512+l
    int h  = blockIdx.y;   // 0..7
    int t  = threadIdx.x;  // 128
    __shared__ float qs[8][97], ks[8][97], vs[8][97], ps[8][8];
    long long base = (long long)bl * 8 * Hh + h * HD;
    if (t < 96) {
        #pragma unroll
        for (int tok = 0; tok < 8; tok++) {
            qs[tok][t] = q[base + tok * Hh + t];
            ks[tok][t] = k[base + tok * Hh + t];
            vs[tok][t] = v[base + tok * Hh + t];
        }
    }
    __syncthreads();
    if (t < 64) {
        int t1 = t >> 3, t2 = t & 7;
        float s = -1e30f;
        if (t2 <= t1) {
            float a = 0.f;
            #pragma unroll 8
            for (int d2 = 0; d2 < 96; d2++) a += qs[t1][d2] * ks[t2][d2];  // FFMA, d ascending
            s = __fdiv_rn(a, SQRT_HD);
        }
        float m = s;
        #pragma unroll
        for (int o2 = 1; o2 <= 4; o2 <<= 1) m = fmaxf(m, __shfl_xor_sync(0xffffffffu, m, o2));
        float e = (t2 <= t1) ? expf(__fsub_rn(s, m)) : 0.0f;
        float sum = e;
        #pragma unroll
        for (int o2 = 1; o2 <= 4; o2 <<= 1) sum += __shfl_xor_sync(0xffffffffu, sum, o2);
        ps[t1][t2] = __fdiv_rn(e, sum);
    }
    __syncthreads();
    if (t < 96) {
        #pragma unroll
        for (int t1 = 0; t1 < 8; t1++) {
            float a = 0.f;
            #pragma unroll
            for (int t2 = 0; t2 < 8; t2++) a += ps[t1][t2] * vs[t2][t];    // FFMA, m ascending
            o[base + t1 * Hh + t] = a;
        }
    }
}

// ---------------------------------------------------------------------------
// Layout permutes: (B,D,L,H) <-> (B,L,D,H)
// ---------------------------------------------------------------------------
__global__ void perm_fwd_kernel(const float* __restrict__ in, float* __restrict__ out)
{
    long long i = (long long)blockIdx.x * 256 + threadIdx.x;
    if (i >= NTOT) return;
    int h = (int)(i % Hh);
    long long r = i / Hh;
    int l = (int)(r % Ll);
    long long bd = r / Ll;
    int dd = (int)(bd % Dd);
    int b  = (int)(bd / Dd);
    out[((long long)(b * Ll + l) * Dd + dd) * Hh + h] = in[i];
}

__global__ void perm_bwd_kernel(const float* __restrict__ in, float* __restrict__ out)
{
    long long i = (long long)blockIdx.x * 256 + threadIdx.x;
    if (i >= NTOT) return;
    int h = (int)(i % Hh);
    long long r = i / Hh;
    int l = (int)(r % Ll);
    long long bd = r / Ll;
    int dd = (int)(bd % Dd);
    int b  = (int)(bd / Dd);
    out[i] = in[((long long)(b * Ll + l) * Dd + dd) * Hh + h];
}

// ---------------------------------------------------------------------------
// Dictionary transpose: (768,4096) -> (4096,768)
// ---------------------------------------------------------------------------
__global__ void transpose_dict_kernel(const float* __restrict__ in, float* __restrict__ out)
{
    __shared__ float tile[32][33];
    int bx = blockIdx.x * 32;   // F dir
    int by = blockIdx.y * 32;   // H dir
    int x = threadIdx.x, y = threadIdx.y;
    #pragma unroll
    for (int j = 0; j < 32; j += 8)
        tile[y + j][x] = in[(long long)(by + y + j) * Ff + bx + x];
    __syncthreads();
    #pragma unroll
    for (int j = 0; j < 32; j += 8)
        out[(long long)(bx + y + j) * Hh + by + x] = tile[x][y + j];
}

// ---------------------------------------------------------------------------
// residual = x[:,1:] - x[:,:-1]  (row-major (B,7,L,H))
// ---------------------------------------------------------------------------
__global__ void res_kernel(const float* __restrict__ x, float* __restrict__ res)
{
    long long i = (long long)blockIdx.x * 256 + threadIdx.x;
    if (i >= RES_TOT) return;
    int h = (int)(i % Hh);
    long long r = i / Hh;
    int l = (int)(r % Ll);
    long long bd = r / Ll;
    int dd = (int)(bd % 7);
    int b  = (int)(bd / 7);
    long long i0 = ((long long)(b * Dd + dd) * Ll + l) * Hh + h;
    res[i] = __fsub_rn(x[i0 + (long long)Ll * Hh], x[i0]);
}

// ---------------------------------------------------------------------------
// Top-64 per row of 4096 (iterative argmax; values relu'd >= 0, ties broken
// by lowest index, matching jax.lax.top_k). Writes z_n directly into d_out,
// records (idx,val) pairs and per-row L1 sum.
// ---------------------------------------------------------------------------
__global__ void topk_kernel(const float* __restrict__ z, float* __restrict__ out,
                            int* __restrict__ tki, float* __restrict__ tkv,
                            float* __restrict__ sparse_part)
{
    long long row = blockIdx.x;
    const float* zr = z + row * Ff;
    __shared__ float rS[Ff];
    __shared__ float wS[Ff];
    __shared__ float bmv[8];
    __shared__ int   bmi[8];
    int t = threadIdx.x;
    for (int i = t; i < Ff; i += 256) { float vv = zr[i]; rS[i] = vv; wS[i] = vv; }
    __syncthreads();

    for (int it = 0; it < TOPK; it++) {
        float bv = -1.0f; int bi = 0x7fffffff;
        for (int i = t; i < Ff; i += 256) {
            float vv = wS[i];
            if (vv > bv || (vv == bv && i < bi)) { bv = vv; bi = i; }
        }
        #pragma unroll
        for (int o = 16; o; o >>= 1) {
            float ov = __shfl_down_sync(0xffffffffu, bv, o);
            int   oi = __shfl_down_sync(0xffffffffu, bi, o);
            if (ov > bv || (ov == bv && oi < bi)) { bv = ov; bi = oi; }
        }
        if ((t & 31) == 0) { bmv[t >> 5] = bv; bmi[t >> 5] = bi; }
        __syncthreads();
        if (t == 0) {
            #pragma unroll
            for (int w = 1; w < 8; w++) {
                if (bmv[w] > bv || (bmv[w] == bv && bmi[w] < bi)) { bv = bmv[w]; bi = bmi[w]; }
            }
            wS[bi] = -1.0f;                 // mark selected
            tki[row * TOPK + it] = bi;
            tkv[row * TOPK + it] = bv;
        }
        __syncthreads();
    }

    // emit full row (selected value or 0) + per-row L1 partial
    float ls = 0.f;
    long long ob = O_Z + row * Ff;
    for (int i = t; i < Ff; i += 256) {
        float vv = (wS[i] < 0.0f) ? rS[i] : 0.0f;
        out[ob + i] = vv;
        ls += vv;
    }
    __shared__ float sp[8];
    #pragma unroll
    for (int o = 16; o; o >>= 1) ls += __shfl_xor_sync(0xffffffffu, ls, o);
    if ((t & 31) == 0) sp[t >> 5] = ls;
    __syncthreads();
    if (t == 0) {
        float s = 0.f;
        #pragma unroll
        for (int w = 0; w < 8; w++) s += sp[w];
        sparse_part[row] = s;
    }
}

// ---------------------------------------------------------------------------
// Sparse decode: x_novel = sum_j z_j * dictT[j], fused with x_hat and
// per-row pred/recon loss partials. Block per row (256 threads, 3 dims each).
// ---------------------------------------------------------------------------
__global__ void novel_kernel(const float* __restrict__ dictT, const float* __restrict__ x,
                             const int* __restrict__ tki, const float* __restrict__ tkv,
                             float* __restrict__ out,
                             float* __restrict__ pred_part, float* __restrict__ recon_part)
{
    long long row = blockIdx.x;     // (b*7+dd)*512 + l
    int t = threadIdx.x;
    __shared__ int   sI[TOPK];
    __shared__ float sV[TOPK];
    if (t < TOPK) { sI[t] = tki[row * TOPK + t]; sV[t] = tkv[row * TOPK + t]; }
    __syncthreads();

    int l = (int)(row % Ll);
    long long bd = row / Ll;
    int dd = (int)(bd % 7);
    int b  = (int)(bd / 7);
    const float* xp = x + ((long long)(b * Dd + dd)     * Ll + l) * Hh;
    const float* xt = x + ((long long)(b * Dd + dd + 1) * Ll + l) * Hh;

    float a0 = 0.f, a1 = 0.f, a2 = 0.f;
    #pragma unroll 4
    for (int j = 0; j < TOPK; j++) {
        float vv = sV[j];
        const float* dr = dictT + (long long)sI[j] * Hh;
        a0 += vv * dr[t];
        a1 += vv * dr[t + 256];
        a2 += vv * dr[t + 512];
    }

    float lr = 0.f, lp = 0.f;
    long long ob = row * Hh;
    float nv[3] = { a0, a1, a2 };
    #pragma unroll
    for (int i = 0; i < 3; i++) {
        int h = t + i * 256;
        float px = xp[h], tg = xt[h];
        float nov = nv[i];
        float xh = __fadd_rn(px, nov);
        out[O_NOVEL + ob + h] = nov;
        out[O_XHAT  + ob + h] = xh;
        float d1 = __fsub_rn(xh, tg); lr += d1 * d1;
        float d2 = __fsub_rn(tg, px); lp += d2 * d2;
    }
    __shared__ float s1[8], s2[8];
    #pragma unroll
    for (int o = 16; o; o >>= 1) {
        lr += __shfl_xor_sync(0xffffffffu, lr, o);
        lp += __shfl_xor_sync(0xffffffffu, lp, o);
    }
    if ((t & 31) == 0) { s1[t >> 5] = lr; s2[t >> 5] = lp; }
    __syncthreads();
    if (t == 0) {
        float r = 0.f, p = 0.f;
        #pragma unroll
        for (int w = 0; w < 8; w++) { r += s1[w]; p += s2[w]; }
        recon_part[row] = r;
        pred_part[row]  = p;
    }
}

// ---------------------------------------------------------------------------
// Final deterministic loss reduction
// ---------------------------------------------------------------------------
__global__ void loss_kernel(const float* __restrict__ pred_part,
                            const float* __restrict__ recon_part,
                            const float* __restrict__ sparse_part,
                            float* __restrict__ out)
{
    int t = threadIdx.x;   // 256
    double sp = 0.0, sr = 0.0, ss = 0.0;
    for (int i = t; i < RES_ROWS; i += 256) {
        sp += (double)pred_part[i];
        sr += (double)recon_part[i];
        ss += (double)sparse_part[i];
    }
    __shared__ double da[256], db[256], dc[256];
    da[t] = sp; db[t] = sr; dc[t] = ss;
    __syncthreads();
    for (int o = 128; o; o >>= 1) {
        if (t < o) { da[t] += da[t + o]; db[t] += db[t + o]; dc[t] += dc[t + o]; }
        __syncthreads();
    }
    if (t == 0) {
        double loss = da[0] / 11010048.0 + db[0] / 11010048.0 + 0.001 * (dc[0] / 58720256.0);
        out[O_LOSS] = (float)loss;
    }
}

// ---------------------------------------------------------------------------
// Host side
// ---------------------------------------------------------------------------
static void sgemm(bool transB, const float* A, const float* B, float* C,
                  const float* add, const float* bias,
                  int M, int N, int K, int lda, int ldb, int ldc,
                  long long sA1, long long sA2, long long sB1, long long sB2,
                  long long sC1, long long sC2, int bdiv, int batch,
                  int relu)
{
    dim3 grid((N + 63) / 64, M / 128, batch);
    if (transB)
        sgemm_kernel<true><<<grid, 128>>>(A, B, C, add, bias, M, N, K, lda, ldb, ldc,
                                          sA1, sA2, sB1, sB2, sC1, sC2, bdiv, relu);
    else
        sgemm_kernel<false><<<grid, 128>>>(A, B, C, add, bias, M, N, K, lda, ldb, ldc,
                                           sA1, sA2, sB1, sB2, sC1, sC2, bdiv, relu);
}

extern "C" void kernel_launch(void* const* d_in, const int* in_sizes, int n_in,
                              void* d_out, int out_size)
{
    const float* zL    = (const float*)d_in[0];
    const float* Wq_l  = (const float*)d_in[1];
    const float* Wk_l  = (const float*)d_in[2];
    const float* Wv_l  = (const float*)d_in[3];
    const float* Wo_l  = (const float*)d_in[4];
    const float* gl    = (const float*)d_in[5];
    const float* bl    = (const float*)d_in[6];
    const float* Wq_d  = (const float*)d_in[7];
    const float* Wk_d  = (const float*)d_in[8];
    const float* Wv_d  = (const float*)d_in[9];
    const float* Wo_d  = (const float*)d_in[10];
    const float* gd    = (const float*)d_in[11];
    const float* bd    = (const float*)d_in[12];
    const float* dict  = (const float*)d_in[13];
    const float* biasn = (const float*)d_in[14];
    float* out = (float*)d_out;

    float *p_ln, *p_q, *p_k, *p_v, *p_attn, *p_x, *p_xt, *p_sc, *p_res, *p_z, *p_dT, *p_tkv, *p_part;
    int *p_tki;
    cudaGetSymbolAddress((void**)&p_ln,   g_ln);
    cudaGetSymbolAddress((void**)&p_q,    g_q);
    cudaGetSymbolAddress((void**)&p_k,    g_k);
    cudaGetSymbolAddress((void**)&p_v,    g_v);
    cudaGetSymbolAddress((void**)&p_attn, g_attn);
    cudaGetSymbolAddress((void**)&p_x,    g_x);
    cudaGetSymbolAddress((void**)&p_xt,   g_xt);
    cudaGetSymbolAddress((void**)&p_sc,   g_sc);
    cudaGetSymbolAddress((void**)&p_res,  g_res);
    cudaGetSymbolAddress((void**)&p_z,    g_z);
    cudaGetSymbolAddress((void**)&p_dT,   g_dictT);
    cudaGetSymbolAddress((void**)&p_tki,  g_tki);
    cudaGetSymbolAddress((void**)&p_tkv,  g_tkv);
    cudaGetSymbolAddress((void**)&p_part, g_part);

    const long long SQH = (long long)Ll * Hh;       // 512*768 seq stride
    const long long SCB = (long long)Ll * Ll;       // 512*512 per-head score size

    // ---------------- Stage A: attention over L (non-causal) ----------------
    ln_kernel<<<ROWS, 256>>>(zL, p_ln, gl, bl);
    sgemm(true, p_ln, Wq_l, p_q, 0, 0, ROWS, Hh, Hh, Hh, Hh, Hh, 0,0,0,0,0,0, 1, 1, 0);
    sgemm(true, p_ln, Wk_l, p_k, 0, 0, ROWS, Hh, Hh, Hh, Hh, Hh, 0,0,0,0,0,0, 1, 1, 0);
    sgemm(true, p_ln, Wv_l, p_v, 0, 0, ROWS, Hh, Hh, Hh, Hh, Hh, 0,0,0,0,0,0, 1, 1, 0);
    // raw scores[seq,head] = Q K^T (scaling done in softmax with IEEE div)
    sgemm(true, p_q, p_k, p_sc, 0, 0, Ll, Ll, HD, Hh, Hh, Ll,
          SQH, HD, SQH, HD, 8*SCB, SCB, NHEAD, 32*NHEAD, 0);
    softmax512_kernel<<<131072, 128>>>(p_sc);
    // attn = P V
    sgemm(false, p_sc, p_v, p_attn, 0, 0, Ll, HD, Ll, Ll, Hh, Hh,
          8*SCB, SCB, SQH, HD, SQH, HD, NHEAD, 32*NHEAD, 0);
    // x = zL + attn Wo^T
    sgemm(true, p_attn, Wo_l, p_x, zL, 0, ROWS, Hh, Hh, Hh, Hh, Hh, 0,0,0,0,0,0, 1, 1, 0);

    // ---------------- Stage B: causal attention over depth D ----------------
    perm_fwd_kernel<<<49152, 256>>>(p_x, p_xt);
    ln_kernel<<<ROWS, 256>>>(p_xt, p_ln, gd, bd);
    sgemm(true, p_ln, Wq_d, p_q, 0, 0, ROWS, Hh, Hh, Hh, Hh, Hh, 0,0,0,0,0,0, 1, 1, 0);
    sgemm(true, p_ln, Wk_d, p_k, 0, 0, ROWS, Hh, Hh, Hh, Hh, Hh, 0,0,0,0,0,0, 1, 1, 0);
    sgemm(true, p_ln, Wv_d, p_v, 0, 0, ROWS, Hh, Hh, Hh, Hh, Hh, 0,0,0,0,0,0, 1, 1, 0);
    attn2_kernel<<<dim3(2048, NHEAD), 128>>>(p_q, p_k, p_v, p_attn);
    sgemm(true, p_attn, Wo_d, p_xt, p_xt, 0, ROWS, Hh, Hh, Hh, Hh, Hh, 0,0,0,0,0,0, 1, 1, 0);
    perm_bwd_kernel<<<49152, 256>>>(p_xt, p_x);

    // ---------------- SAE head ----------------
    transpose_dict_kernel<<<dim3(128, 24), dim3(32, 8)>>>(dict, p_dT);
    res_kernel<<<43008, 256>>>(p_x, p_res);
    // z_dense = relu(res @ dict + bias)   (strict k-seq FMA -> correlates with ref)
    sgemm(false, p_res, dict, p_z, 0, biasn, RES_ROWS, Ff, Hh, Hh, Ff, Ff,
          0,0,0,0,0,0, 1, 1, 1);
    topk_kernel<<<RES_ROWS, 256>>>(p_z, out, p_tki, p_tkv, p_part + 2 * RES_ROWS);
    novel_kernel<<<RES_ROWS, 256>>>(p_dT, p_x, p_tki, p_tkv, out,
                                    p_part, p_part + RES_ROWS);
    loss_kernel<<<1, 256>>>(p_part, p_part + RES_ROWS, p_part + 2 * RES_ROWS, out);
}

// round 13
// speedup vs baseline: 1.0669x; 1.0359x over previous
#include <cuda_runtime.h>
#include <cuda_bf16.h>
#include <math.h>

// ---------------------------------------------------------------------------
// Problem constants
// ---------------------------------------------------------------------------
#define Bsz   4
#define Dd    8
#define Ll    512
#define Hh    768
#define Ff    4096
#define NHEAD 8
#define HD    96         // head dim
#define TOPK  64
#define ROWS  16384      // B*D*L rows of H
#define NTOT  12582912LL // 16384*768
#define RES_ROWS 14336   // B*(D-1)*L
#define RES_TOT  11010048LL  // 14336*768
#define Z_TOT    58720256LL  // 14336*4096

#define O_LOSS  0LL
#define O_XHAT  1LL
#define O_NOVEL 11010049LL   // 1 + 11010048
#define O_Z     22020097LL   // 1 + 2*11010048

#define SQRT_HD 9.79795897113271239f   // fp32(sqrt(96)), == sqrtf(96.0f)

// ---------------------------------------------------------------------------
// Static device workspace (allocation-free rule: __device__ globals)
// ---------------------------------------------------------------------------
__device__ float g_ln  [NTOT];
__device__ float g_q   [NTOT];
__device__ float g_k   [NTOT];
__device__ float g_v   [NTOT];
__device__ float g_attn[NTOT];
__device__ float g_x   [NTOT];
__device__ float g_xt  [NTOT];
__device__ float g_sc  [67108864];    // 256 * 512 * 512 scores
__device__ float g_res [RES_TOT];
__device__ float g_z   [Z_TOT];
__device__ float g_dictT[Ff * Hh];
__device__ int   g_tki [RES_ROWS * TOPK];
__device__ float g_tkv [RES_ROWS * TOPK];
__device__ float g_part[3 * RES_ROWS]; // pred | recon | sparse partials

// ---------------------------------------------------------------------------
// LayerNorm: one block per row of 768, 256 threads. Two-pass variance
// (reference's literal mean(square(x - mu))), libdevice rsqrtf, IEEE
// divisions, NO fma contraction in the epilogue. BIT-PATH IS LOAD-BEARING.
// ---------------------------------------------------------------------------
__global__ void ln_kernel(const float* __restrict__ x, float* __restrict__ y,
                          const float* __restrict__ gg, const float* __restrict__ bb)
{
    long long row = blockIdx.x;
    const float* xr = x + row * Hh;
    float* yr = y + row * Hh;
    int t = threadIdx.x;
    float v0 = xr[t], v1 = xr[t + 256], v2 = xr[t + 512];
    __shared__ float sa[8], sq[8];

    float s = __fadd_rn(__fadd_rn(v0, v1), v2);
    #pragma unroll
    for (int o = 16; o; o >>= 1) s += __shfl_xor_sync(0xffffffffu, s, o);
    if ((t & 31) == 0) sa[t >> 5] = s;
    __syncthreads();
    s = 0.f;
    #pragma unroll
    for (int w = 0; w < 8; w++) s += sa[w];
    float mu = __fdiv_rn(s, 768.0f);

    float d0 = __fsub_rn(v0, mu), d1 = __fsub_rn(v1, mu), d2 = __fsub_rn(v2, mu);
    float s2 = __fadd_rn(__fadd_rn(__fmul_rn(d0, d0), __fmul_rn(d1, d1)), __fmul_rn(d2, d2));
    #pragma unroll
    for (int o = 16; o; o >>= 1) s2 += __shfl_xor_sync(0xffffffffu, s2, o);
    if ((t & 31) == 0) sq[t >> 5] = s2;
    __syncthreads();
    s2 = 0.f;
    #pragma unroll
    for (int w = 0; w < 8; w++) s2 += sq[w];
    float var  = __fdiv_rn(s2, 768.0f);
    float rstd = rsqrtf(__fadd_rn(var, 1e-5f));

    yr[t]       = __fadd_rn(__fmul_rn(__fmul_rn(d0, rstd), gg[t]),       bb[t]);
    yr[t + 256] = __fadd_rn(__fmul_rn(__fmul_rn(d1, rstd), gg[t + 256]), bb[t + 256]);
    yr[t + 512] = __fadd_rn(__fmul_rn(__fmul_rn(d2, rstd), gg[t + 512]), bb[t + 512]);
}

// ---------------------------------------------------------------------------
// Tiled SGEMM, STRICT k-ascending fp32 FMA accumulation per output element.
// Per-element rounding chain identical to R9 (correlated with the reference
// GEMM — protects the top-k boundary). DO NOT alter the order.
//
// R12: BM=128, BN=64, BK=16, 128 threads, 8x8 fragment — with a ZERO-
// BANK-CONFLICT smem schedule (R9/R10/R11 all burned l1tex on 4-way store
// conflicts in the transpose and 2-way b-fragment read conflicts):
//   * A tile: thread t loads row m0+t strip k0..k0+15 (4x float4, fully
//     sectored) and stores scalars to As[k][t] -> 32 distinct banks/warp.
//   * B tile (transB): n = i&63 -> 32 distinct banks/warp.
//   * b-fragment split: b[0..3]=Bs[k][tx*4], b[4..7]=Bs[k][tx*4+32] ->
//     phase covers floats 0..31 -> conflict-free. acc column j maps to
//     n = tx*4+j (j<4) and 32+tx*4+(j-4) (j>=4).
//   * a-fragment As[k][ty*8..] is intra-phase broadcast (free).
//   TRANSB=true : C[M,N] = A[M,K] * B[N,K]^T
//   TRANSB=false: C[M,N] = A[M,K] * B[K,N]
// Requires M % 128 == 0, K % 16 == 0; N guarded at float4 grain.
// ---------------------------------------------------------------------------
template<bool TRANSB>
__global__ void __launch_bounds__(128, 4)
sgemm_kernel(const float* __restrict__ Ag, const float* __restrict__ Bg,
             float* __restrict__ Cg,
             const float* __restrict__ addsrc, const float* __restrict__ bias,
             int M, int N, int K, int lda, int ldb, int ldc,
             long long sA1, long long sA2, long long sB1, long long sB2,
             long long sC1, long long sC2, int bdiv,
             int relu)
{
    int z  = blockIdx.z;
    int z1 = z / bdiv, z2 = z - z1 * bdiv;
    const float* A = Ag + z1 * sA1 + z2 * sA2;
    const float* B = Bg + z1 * sB1 + z2 * sB2;
    float*       C = Cg + z1 * sC1 + z2 * sC2;
    const float* add = addsrc ? (addsrc + z1 * sC1 + z2 * sC2) : (const float*)0;

    __shared__ float As[16][128];
    __shared__ float Bs[16][64];

    int m0 = blockIdx.y * 128;
    int n0 = blockIdx.x * 64;
    int t  = threadIdx.x;          // 128 threads
    int tx = t & 7, ty = t >> 3;   // fragment grid

    float acc[8][8];
    #pragma unroll
    for (int i = 0; i < 8; i++)
        #pragma unroll
        for (int j = 0; j < 8; j++) acc[i][j] = 0.f;

    for (int k0 = 0; k0 < K; k0 += 16) {
        // ---- A tile: thread t owns row m0+t, k-strip of 16 (4x float4).
        //      Stores As[k][t]: warp lanes hit 32 distinct banks. ----
        {
            const float* ap = A + (long long)(m0 + t) * lda + k0;
            #pragma unroll
            for (int r = 0; r < 4; r++) {
                float4 a4 = *(const float4*)(ap + r * 4);
                As[r*4+0][t] = a4.x;
                As[r*4+1][t] = a4.y;
                As[r*4+2][t] = a4.z;
                As[r*4+3][t] = a4.w;
            }
        }
        // ---- B tile ----
        if (TRANSB) {
            // 64 rows x 16 k: i -> n = i&63 (32 distinct banks/warp), kq = i>>6
            #pragma unroll
            for (int r = 0; r < 2; r++) {
                int i  = t + r * 128;
                int n  = i & 63, kq = i >> 6;
                float4 b4 = make_float4(0.f, 0.f, 0.f, 0.f);
                if (n0 + n < N)
                    b4 = *(const float4*)(B + (long long)(n0 + n) * ldb + (k0 + kq * 4));
                Bs[kq*4+0][n] = b4.x;
                Bs[kq*4+1][n] = b4.y;
                Bs[kq*4+2][n] = b4.z;
                Bs[kq*4+3][n] = b4.w;
            }
        } else {
            // k-major: contiguous float4 stores, already conflict-free
            #pragma unroll
            for (int r = 0; r < 2; r++) {
                int i  = t + r * 128;
                int rk = i >> 4, nq = i & 15;
                float4 b4 = make_float4(0.f, 0.f, 0.f, 0.f);
                if (n0 + nq * 4 < N)
                    b4 = *(const float4*)(B + (long long)(k0 + rk) * ldb + (n0 + nq * 4));
                *(float4*)&Bs[rk][nq * 4] = b4;
            }
        }
        __syncthreads();
        #pragma unroll
        for (int k = 0; k < 16; k++) {
            float a[8], b[8];
            *(float4*)&a[0] = *(const float4*)&As[k][ty * 8];
            *(float4*)&a[4] = *(const float4*)&As[k][ty * 8 + 4];
            *(float4*)&b[0] = *(const float4*)&Bs[k][tx * 4];        // n = tx*4 + j
            *(float4*)&b[4] = *(const float4*)&Bs[k][tx * 4 + 32];   // n = 32 + tx*4 + j
            #pragma unroll
            for (int i = 0; i < 8; i++)
                #pragma unroll
                for (int j = 0; j < 8; j++)
                    acc[i][j] += a[i] * b[j];   // FFMA, strict k order
        }
        __syncthreads();
    }

    // ---- epilogue: 8 rows x 2 float4 per thread (split columns) ----
    #pragma unroll
    for (int i = 0; i < 8; i++) {
        long long m = m0 + ty * 8 + i;
        #pragma unroll
        for (int q = 0; q < 2; q++) {
            int n = n0 + q * 32 + tx * 4;
            if (n < N) {
                float4 r;
                r.x = acc[i][q*4+0]; r.y = acc[i][q*4+1];
                r.z = acc[i][q*4+2]; r.w = acc[i][q*4+3];
                if (bias) {
                    r.x = __fadd_rn(r.x, bias[n]);   r.y = __fadd_rn(r.y, bias[n+1]);
                    r.z = __fadd_rn(r.z, bias[n+2]); r.w = __fadd_rn(r.w, bias[n+3]);
                }
                if (add) {
                    float4 a4 = *(const float4*)(add + m * ldc + n);
                    r.x = __fadd_rn(r.x, a4.x); r.y = __fadd_rn(r.y, a4.y);
                    r.z = __fadd_rn(r.z, a4.z); r.w = __fadd_rn(r.w, a4.w);
                }
                if (relu) {
                    r.x = fmaxf(r.x, 0.f); r.y = fmaxf(r.y, 0.f);
                    r.z = fmaxf(r.z, 0.f); r.w = fmaxf(r.w, 0.f);
                }
                *(float4*)(C + m * ldc + n) = r;
            }
        }
    }
}

// ---------------------------------------------------------------------------
// Row softmax over 512 (non-causal), in place. One block (128 thr) per row.
// IEEE div by sqrt(96), libdevice expf, IEEE normalize. BIT-PATH LOAD-BEARING.
// ---------------------------------------------------------------------------
__global__ void softmax512_kernel(float* __restrict__ sc)
{
    long long row = blockIdx.x;
    float* p = sc + row * 512;
    int t = threadIdx.x;
    float v[4];
    #pragma unroll
    for (int i = 0; i < 4; i++) v[i] = __fdiv_rn(p[t + i * 128], SQRT_HD);
    float m = fmaxf(fmaxf(v[0], v[1]), fmaxf(v[2], v[3]));
    __shared__ float sm[4], ss[4];
    #pragma unroll
    for (int o = 16; o; o >>= 1) m = fmaxf(m, __shfl_xor_sync(0xffffffffu, m, o));
    if ((t & 31) == 0) sm[t >> 5] = m;
    __syncthreads();
    m = fmaxf(fmaxf(sm[0], sm[1]), fmaxf(sm[2], sm[3]));
    float s = 0.f;
    #pragma unroll
    for (int i = 0; i < 4; i++) { v[i] = expf(__fsub_rn(v[i], m)); s += v[i]; }
    #pragma unroll
    for (int o = 16; o; o >>= 1) s += __shfl_xor_sync(0xffffffffu, s, o);
    if ((t & 31) == 0) ss[t >> 5] = s;
    __syncthreads();
    s = ss[0] + ss[1] + ss[2] + ss[3];
    #pragma unroll
    for (int i = 0; i < 4; i++) p[t + i * 128] = __fdiv_rn(v[i], s);
}

// ---------------------------------------------------------------------------
// Tiny causal attention over depth (D=8 tokens). Block = (bl, head), 128 thr.
// ---------------------------------------------------------------------------
__global__ void attn2_kernel(const float* __restrict__ q, const float* __restrict__ k,
                             const float* __restrict__ v, float* __restrict__ o)
{
    int bl = blockIdx.x;   // 0..2047 = b*512+l
    int h  = blockIdx.y;   // 0..7
    int t  = threadIdx.x;  // 128
    __shared__ float qs[8][97], ks[8][97], vs[8][97], ps[8][8];
    long long base = (long long)bl * 8 * Hh + h * HD;
    if (t < 96) {
        #pragma unroll
        for (int tok = 0; tok < 8; tok++) {
            qs[tok][t] = q[base + tok * Hh + t];
            ks[tok][t] = k[base + tok * Hh + t];
            vs[tok][t] = v[base + tok * Hh + t];
        }
    }
    __syncthreads();
    if (t < 64) {
        int t1 = t >> 3, t2 = t & 7;
        float s = -1e30f;
        if (t2 <= t1) {
            float a = 0.f;
            #pragma unroll 8
            for (int d2 = 0; d2 < 96; d2++) a += qs[t1][d2] * ks[t2][d2];  // FFMA, d ascending
            s = __fdiv_rn(a, SQRT_HD);
        }
        float m = s;
        #pragma unroll
        for (int o2 = 1; o2 <= 4; o2 <<= 1) m = fmaxf(m, __shfl_xor_sync(0xffffffffu, m, o2));
        float e = (t2 <= t1) ? expf(__fsub_rn(s, m)) : 0.0f;
        float sum = e;
        #pragma unroll
        for (int o2 = 1; o2 <= 4; o2 <<= 1) sum += __shfl_xor_sync(0xffffffffu, sum, o2);
        ps[t1][t2] = __fdiv_rn(e, sum);
    }
    __syncthreads();
    if (t < 96) {
        #pragma unroll
        for (int t1 = 0; t1 < 8; t1++) {
            float a = 0.f;
            #pragma unroll
            for (int t2 = 0; t2 < 8; t2++) a += ps[t1][t2] * vs[t2][t];    // FFMA, m ascending
            o[base + t1 * Hh + t] = a;
        }
    }
}

// ---------------------------------------------------------------------------
// Layout permutes: (B,D,L,H) <-> (B,L,D,H)
// ---------------------------------------------------------------------------
__global__ void perm_fwd_kernel(const float* __restrict__ in, float* __restrict__ out)
{
    long long i = (long long)blockIdx.x * 256 + threadIdx.x;
    if (i >= NTOT) return;
    int h = (int)(i % Hh);
    long long r = i / Hh;
    int l = (int)(r % Ll);
    long long bd = r / Ll;
    int dd = (int)(bd % Dd);
    int b  = (int)(bd / Dd);
    out[((long long)(b * Ll + l) * Dd + dd) * Hh + h] = in[i];
}

__global__ void perm_bwd_kernel(const float* __restrict__ in, float* __restrict__ out)
{
    long long i = (long long)blockIdx.x * 256 + threadIdx.x;
    if (i >= NTOT) return;
    int h = (int)(i % Hh);
    long long r = i / Hh;
    int l = (int)(r % Ll);
    long long bd = r / Ll;
    int dd = (int)(bd % Dd);
    int b  = (int)(bd / Dd);
    out[i] = in[((long long)(b * Ll + l) * Dd + dd) * Hh + h];
}

// ---------------------------------------------------------------------------
// Dictionary transpose: (768,4096) -> (4096,768)
// ---------------------------------------------------------------------------
__global__ void transpose_dict_kernel(const float* __restrict__ in, float* __restrict__ out)
{
    __shared__ float tile[32][33];
    int bx = blockIdx.x * 32;   // F dir
    int by = blockIdx.y * 32;   // H dir
    int x = threadIdx.x, y = threadIdx.y;
    #pragma unroll
    for (int j = 0; j < 32; j += 8)
        tile[y + j][x] = in[(long long)(by + y + j) * Ff + bx + x];
    __syncthreads();
    #pragma unroll
    for (int j = 0; j < 32; j += 8)
        out[(long long)(bx + y + j) * Hh + by + x] = tile[x][y + j];
}

// ---------------------------------------------------------------------------
// residual = x[:,1:] - x[:,:-1]  (row-major (B,7,L,H))
// ---------------------------------------------------------------------------
__global__ void res_kernel(const float* __restrict__ x, float* __restrict__ res)
{
    long long i = (long long)blockIdx.x * 256 + threadIdx.x;
    if (i >= RES_TOT) return;
    int h = (int)(i % Hh);
    long long r = i / Hh;
    int l = (int)(r % Ll);
    long long bd = r / Ll;
    int dd = (int)(bd % 7);
    int b  = (int)(bd / 7);
    long long i0 = ((long long)(b * Dd + dd) * Ll + l) * Hh + h;
    res[i] = __fsub_rn(x[i0 + (long long)Ll * Hh], x[i0]);
}

// ---------------------------------------------------------------------------
// Top-64 per row of 4096 (iterative argmax; values relu'd >= 0, ties broken
// by lowest index, matching jax.lax.top_k). Writes z_n directly into d_out,
// records (idx,val) pairs and per-row L1 sum.
// ---------------------------------------------------------------------------
__global__ void topk_kernel(const float* __restrict__ z, float* __restrict__ out,
                            int* __restrict__ tki, float* __restrict__ tkv,
                            float* __restrict__ sparse_part)
{
    long long row = blockIdx.x;
    const float* zr = z + row * Ff;
    __shared__ float rS[Ff];
    __shared__ float wS[Ff];
    __shared__ float bmv[8];
    __shared__ int   bmi[8];
    int t = threadIdx.x;
    for (int i = t; i < Ff; i += 256) { float vv = zr[i]; rS[i] = vv; wS[i] = vv; }
    __syncthreads();

    for (int it = 0; it < TOPK; it++) {
        float bv = -1.0f; int bi = 0x7fffffff;
        for (int i = t; i < Ff; i += 256) {
            float vv = wS[i];
            if (vv > bv || (vv == bv && i < bi)) { bv = vv; bi = i; }
        }
        #pragma unroll
        for (int o = 16; o; o >>= 1) {
            float ov = __shfl_down_sync(0xffffffffu, bv, o);
            int   oi = __shfl_down_sync(0xffffffffu, bi, o);
            if (ov > bv || (ov == bv && oi < bi)) { bv = ov; bi = oi; }
        }
        if ((t & 31) == 0) { bmv[t >> 5] = bv; bmi[t >> 5] = bi; }
        __syncthreads();
        if (t == 0) {
            #pragma unroll
            for (int w = 1; w < 8; w++) {
                if (bmv[w] > bv || (bmv[w] == bv && bmi[w] < bi)) { bv = bmv[w]; bi = bmi[w]; }
            }
            wS[bi] = -1.0f;                 // mark selected
            tki[row * TOPK + it] = bi;
            tkv[row * TOPK + it] = bv;
        }
        __syncthreads();
    }

    // emit full row (selected value or 0) + per-row L1 partial
    float ls = 0.f;
    long long ob = O_Z + row * Ff;
    for (int i = t; i < Ff; i += 256) {
        float vv = (wS[i] < 0.0f) ? rS[i] : 0.0f;
        out[ob + i] = vv;
        ls += vv;
    }
    __shared__ float sp[8];
    #pragma unroll
    for (int o = 16; o; o >>= 1) ls += __shfl_xor_sync(0xffffffffu, ls, o);
    if ((t & 31) == 0) sp[t >> 5] = ls;
    __syncthreads();
    if (t == 0) {
        float s = 0.f;
        #pragma unroll
        for (int w = 0; w < 8; w++) s += sp[w];
        sparse_part[row] = s;
    }
}

// ---------------------------------------------------------------------------
// Sparse decode: x_novel = sum_j z_j * dictT[j], fused with x_hat and
// per-row pred/recon loss partials. Block per row (256 threads, 3 dims each).
// ---------------------------------------------------------------------------
__global__ void novel_kernel(const float* __restrict__ dictT, const float* __restrict__ x,
                             const int* __restrict__ tki, const float* __restrict__ tkv,
                             float* __restrict__ out,
                             float* __restrict__ pred_part, float* __restrict__ recon_part)
{
    long long row = blockIdx.x;     // (b*7+dd)*512 + l
    int t = threadIdx.x;
    __shared__ int   sI[TOPK];
    __shared__ float sV[TOPK];
    if (t < TOPK) { sI[t] = tki[row * TOPK + t]; sV[t] = tkv[row * TOPK + t]; }
    __syncthreads();

    int l = (int)(row % Ll);
    long long bd = row / Ll;
    int dd = (int)(bd % 7);
    int b  = (int)(bd / 7);
    const float* xp = x + ((long long)(b * Dd + dd)     * Ll + l) * Hh;
    const float* xt = x + ((long long)(b * Dd + dd + 1) * Ll + l) * Hh;

    float a0 = 0.f, a1 = 0.f, a2 = 0.f;
    #pragma unroll 4
    for (int j = 0; j < TOPK; j++) {
        float vv = sV[j];
        const float* dr = dictT + (long long)sI[j] * Hh;
        a0 += vv * dr[t];
        a1 += vv * dr[t + 256];
        a2 += vv * dr[t + 512];
    }

    float lr = 0.f, lp = 0.f;
    long long ob = row * Hh;
    float nv[3] = { a0, a1, a2 };
    #pragma unroll
    for (int i = 0; i < 3; i++) {
        int h = t + i * 256;
        float px = xp[h], tg = xt[h];
        float nov = nv[i];
        float xh = __fadd_rn(px, nov);
        out[O_NOVEL + ob + h] = nov;
        out[O_XHAT  + ob + h] = xh;
        float d1 = __fsub_rn(xh, tg); lr += d1 * d1;
        float d2 = __fsub_rn(tg, px); lp += d2 * d2;
    }
    __shared__ float s1[8], s2[8];
    #pragma unroll
    for (int o = 16; o; o >>= 1) {
        lr += __shfl_xor_sync(0xffffffffu, lr, o);
        lp += __shfl_xor_sync(0xffffffffu, lp, o);
    }
    if ((t & 31) == 0) { s1[t >> 5] = lr; s2[t >> 5] = lp; }
    __syncthreads();
    if (t == 0) {
        float r = 0.f, p = 0.f;
        #pragma unroll
        for (int w = 0; w < 8; w++) { r += s1[w]; p += s2[w]; }
        recon_part[row] = r;
        pred_part[row]  = p;
    }
}

// ---------------------------------------------------------------------------
// Final deterministic loss reduction
// ---------------------------------------------------------------------------
__global__ void loss_kernel(const float* __restrict__ pred_part,
                            const float* __restrict__ recon_part,
                            const float* __restrict__ sparse_part,
                            float* __restrict__ out)
{
    int t = threadIdx.x;   // 256
    double sp = 0.0, sr = 0.0, ss = 0.0;
    for (int i = t; i < RES_ROWS; i += 256) {
        sp += (double)pred_part[i];
        sr += (double)recon_part[i];
        ss += (double)sparse_part[i];
    }
    __shared__ double da[256], db[256], dc[256];
    da[t] = sp; db[t] = sr; dc[t] = ss;
    __syncthreads();
    for (int o = 128; o; o >>= 1) {
        if (t < o) { da[t] += da[t + o]; db[t] += db[t + o]; dc[t] += dc[t + o]; }
        __syncthreads();
    }
    if (t == 0) {
        double loss = da[0] / 11010048.0 + db[0] / 11010048.0 + 0.001 * (dc[0] / 58720256.0);
        out[O_LOSS] = (float)loss;
    }
}

// ---------------------------------------------------------------------------
// Host side
// ---------------------------------------------------------------------------
static void sgemm(bool transB, const float* A, const float* B, float* C,
                  const float* add, const float* bias,
                  int M, int N, int K, int lda, int ldb, int ldc,
                  long long sA1, long long sA2, long long sB1, long long sB2,
                  long long sC1, long long sC2, int bdiv, int batch,
                  int relu)
{
    dim3 grid((N + 63) / 64, M / 128, batch);
    if (transB)
        sgemm_kernel<true><<<grid, 128>>>(A, B, C, add, bias, M, N, K, lda, ldb, ldc,
                                          sA1, sA2, sB1, sB2, sC1, sC2, bdiv, relu);
    else
        sgemm_kernel<false><<<grid, 128>>>(A, B, C, add, bias, M, N, K, lda, ldb, ldc,
                                           sA1, sA2, sB1, sB2, sC1, sC2, bdiv, relu);
}

extern "C" void kernel_launch(void* const* d_in, const int* in_sizes, int n_in,
                              void* d_out, int out_size)
{
    const float* zL    = (const float*)d_in[0];
    const float* Wq_l  = (const float*)d_in[1];
    const float* Wk_l  = (const float*)d_in[2];
    const float* Wv_l  = (const float*)d_in[3];
    const float* Wo_l  = (const float*)d_in[4];
    const float* gl    = (const float*)d_in[5];
    const float* bl    = (const float*)d_in[6];
    const float* Wq_d  = (const float*)d_in[7];
    const float* Wk_d  = (const float*)d_in[8];
    const float* Wv_d  = (const float*)d_in[9];
    const float* Wo_d  = (const float*)d_in[10];
    const float* gd    = (const float*)d_in[11];
    const float* bd    = (const float*)d_in[12];
    const float* dict  = (const float*)d_in[13];
    const float* biasn = (const float*)d_in[14];
    float* out = (float*)d_out;

    float *p_ln, *p_q, *p_k, *p_v, *p_attn, *p_x, *p_xt, *p_sc, *p_res, *p_z, *p_dT, *p_tkv, *p_part;
    int *p_tki;
    cudaGetSymbolAddress((void**)&p_ln,   g_ln);
    cudaGetSymbolAddress((void**)&p_q,    g_q);
    cudaGetSymbolAddress((void**)&p_k,    g_k);
    cudaGetSymbolAddress((void**)&p_v,    g_v);
    cudaGetSymbolAddress((void**)&p_attn, g_attn);
    cudaGetSymbolAddress((void**)&p_x,    g_x);
    cudaGetSymbolAddress((void**)&p_xt,   g_xt);
    cudaGetSymbolAddress((void**)&p_sc,   g_sc);
    cudaGetSymbolAddress((void**)&p_res,  g_res);
    cudaGetSymbolAddress((void**)&p_z,    g_z);
    cudaGetSymbolAddress((void**)&p_dT,   g_dictT);
    cudaGetSymbolAddress((void**)&p_tki,  g_tki);
    cudaGetSymbolAddress((void**)&p_tkv,  g_tkv);
    cudaGetSymbolAddress((void**)&p_part, g_part);

    const long long SQH = (long long)Ll * Hh;       // 512*768 seq stride
    const long long SCB = (long long)Ll * Ll;       // 512*512 per-head score size

    // ---------------- Stage A: attention over L (non-causal) ----------------
    ln_kernel<<<ROWS, 256>>>(zL, p_ln, gl, bl);
    sgemm(true, p_ln, Wq_l, p_q, 0, 0, ROWS, Hh, Hh, Hh, Hh, Hh, 0,0,0,0,0,0, 1, 1, 0);
    sgemm(true, p_ln, Wk_l, p_k, 0, 0, ROWS, Hh, Hh, Hh, Hh, Hh, 0,0,0,0,0,0, 1, 1, 0);
    sgemm(true, p_ln, Wv_l, p_v, 0, 0, ROWS, Hh, Hh, Hh, Hh, Hh, 0,0,0,0,0,0, 1, 1, 0);
    // raw scores[seq,head] = Q K^T (scaling done in softmax with IEEE div)
    sgemm(true, p_q, p_k, p_sc, 0, 0, Ll, Ll, HD, Hh, Hh, Ll,
          SQH, HD, SQH, HD, 8*SCB, SCB, NHEAD, 32*NHEAD, 0);
    softmax512_kernel<<<131072, 128>>>(p_sc);
    // attn = P V
    sgemm(false, p_sc, p_v, p_attn, 0, 0, Ll, HD, Ll, Ll, Hh, Hh,
          8*SCB, SCB, SQH, HD, SQH, HD, NHEAD, 32*NHEAD, 0);
    // x = zL + attn Wo^T
    sgemm(true, p_attn, Wo_l, p_x, zL, 0, ROWS, Hh, Hh, Hh, Hh, Hh, 0,0,0,0,0,0, 1, 1, 0);

    // ---------------- Stage B: causal attention over depth D ----------------
    perm_fwd_kernel<<<49152, 256>>>(p_x, p_xt);
    ln_kernel<<<ROWS, 256>>>(p_xt, p_ln, gd, bd);
    sgemm(true, p_ln, Wq_d, p_q, 0, 0, ROWS, Hh, Hh, Hh, Hh, Hh, 0,0,0,0,0,0, 1, 1, 0);
    sgemm(true, p_ln, Wk_d, p_k, 0, 0, ROWS, Hh, Hh, Hh, Hh, Hh, 0,0,0,0,0,0, 1, 1, 0);
    sgemm(true, p_ln, Wv_d, p_v, 0, 0, ROWS, Hh, Hh, Hh, Hh, Hh, 0,0,0,0,0,0, 1, 1, 0);
    attn2_kernel<<<dim3(2048, NHEAD), 128>>>(p_q, p_k, p_v, p_attn);
    sgemm(true, p_attn, Wo_d, p_xt, p_xt, 0, ROWS, Hh, Hh, Hh, Hh, Hh, 0,0,0,0,0,0, 1, 1, 0);
    perm_bwd_kernel<<<49152, 256>>>(p_xt, p_x);

    // ---------------- SAE head ----------------
    transpose_dict_kernel<<<dim3(128, 24), dim3(32, 8)>>>(dict, p_dT);
    res_kernel<<<43008, 256>>>(p_x, p_res);
    // z_dense = relu(res @ dict + bias)   (strict k-seq FMA -> correlates with ref)
    sgemm(false, p_res, dict, p_z, 0, biasn, RES_ROWS, Ff, Hh, Hh, Ff, Ff,
          0,0,0,0,0,0, 1, 1, 1);
    topk_kernel<<<RES_ROWS, 256>>>(p_z, out, p_tki, p_tkv, p_part + 2 * RES_ROWS);
    novel_kernel<<<RES_ROWS, 256>>>(p_dT, p_x, p_tki, p_tkv, out,
                                    p_part, p_part + RES_ROWS);
    loss_kernel<<<1, 256>>>(p_part, p_part + RES_ROWS, p_part + 2 * RES_ROWS, out);
}

// round 14
// speedup vs baseline: 1.2512x; 1.1727x over previous
#include <cuda_runtime.h>
#include <cuda_bf16.h>
#include <math.h>

// ---------------------------------------------------------------------------
// Problem constants
// ---------------------------------------------------------------------------
#define Bsz   4
#define Dd    8
#define Ll    512
#define Hh    768
#define Ff    4096
#define NHEAD 8
#define HD    96         // head dim
#define TOPK  64
#define ROWS  16384      // B*D*L rows of H
#define QS    2304       // fused q|k|v row stride
#define NTOT  12582912LL // 16384*768
#define RES_ROWS 14336   // B*(D-1)*L
#define RES_TOT  11010048LL  // 14336*768
#define Z_TOT    58720256LL  // 14336*4096

#define O_LOSS  0LL
#define O_XHAT  1LL
#define O_NOVEL 11010049LL   // 1 + 11010048
#define O_Z     22020097LL   // 1 + 2*11010048

#define SQRT_HD 9.79795897113271239f   // fp32(sqrt(96)), == sqrtf(96.0f)

// ---------------------------------------------------------------------------
// Static device workspace (allocation-free rule: __device__ globals)
// ---------------------------------------------------------------------------
__device__ float g_ln  [NTOT];
__device__ float g_qkv [16384 * 2304];   // fused q|k|v, 151 MB
__device__ float g_wcat[3 * Hh * Hh];    // concatenated Wq|Wk|Wv
__device__ float g_attn[NTOT];
__device__ float g_x   [NTOT];
__device__ float g_xt  [NTOT];
__device__ float g_sc  [67108864];       // 256 * 512 * 512 scores
__device__ float g_res [RES_TOT];
__device__ float g_z   [Z_TOT];
__device__ float g_dictT[Ff * Hh];
__device__ int   g_tki [RES_ROWS * TOPK];
__device__ float g_tkv [RES_ROWS * TOPK];
__device__ float g_part[3 * RES_ROWS];   // pred | recon | sparse partials

// ---------------------------------------------------------------------------
// LayerNorm: one block per row of 768, 256 threads. Two-pass variance
// (reference's literal mean(square(x - mu))), libdevice rsqrtf, IEEE
// divisions, NO fma contraction in the epilogue. BIT-PATH IS LOAD-BEARING.
// ---------------------------------------------------------------------------
__global__ void ln_kernel(const float* __restrict__ x, float* __restrict__ y,
                          const float* __restrict__ gg, const float* __restrict__ bb)
{
    long long row = blockIdx.x;
    const float* xr = x + row * Hh;
    float* yr = y + row * Hh;
    int t = threadIdx.x;
    float v0 = xr[t], v1 = xr[t + 256], v2 = xr[t + 512];
    __shared__ float sa[8], sq[8];

    float s = __fadd_rn(__fadd_rn(v0, v1), v2);
    #pragma unroll
    for (int o = 16; o; o >>= 1) s += __shfl_xor_sync(0xffffffffu, s, o);
    if ((t & 31) == 0) sa[t >> 5] = s;
    __syncthreads();
    s = 0.f;
    #pragma unroll
    for (int w = 0; w < 8; w++) s += sa[w];
    float mu = __fdiv_rn(s, 768.0f);

    float d0 = __fsub_rn(v0, mu), d1 = __fsub_rn(v1, mu), d2 = __fsub_rn(v2, mu);
    float s2 = __fadd_rn(__fadd_rn(__fmul_rn(d0, d0), __fmul_rn(d1, d1)), __fmul_rn(d2, d2));
    #pragma unroll
    for (int o = 16; o; o >>= 1) s2 += __shfl_xor_sync(0xffffffffu, s2, o);
    if ((t & 31) == 0) sq[t >> 5] = s2;
    __syncthreads();
    s2 = 0.f;
    #pragma unroll
    for (int w = 0; w < 8; w++) s2 += sq[w];
    float var  = __fdiv_rn(s2, 768.0f);
    float rstd = rsqrtf(__fadd_rn(var, 1e-5f));

    yr[t]       = __fadd_rn(__fmul_rn(__fmul_rn(d0, rstd), gg[t]),       bb[t]);
    yr[t + 256] = __fadd_rn(__fmul_rn(__fmul_rn(d1, rstd), gg[t + 256]), bb[t + 256]);
    yr[t + 512] = __fadd_rn(__fmul_rn(__fmul_rn(d2, rstd), gg[t + 512]), bb[t + 512]);
}

// ---------------------------------------------------------------------------
// Tiled SGEMM, STRICT k-ascending fp32 FMA accumulation per output element.
// Per-element rounding chain identical to R9 (correlated with the reference
// GEMM — protects the top-k boundary). DO NOT alter the order.
//
// R14: BM=128, BN=64, BK=32, 128 threads, 8x8 fragment, conflict-free smem
// schedule (R12). BK=32 halves the barriers per k and doubles the FFMA run
// between syncs — ncu showed both pipes under-utilized (fma 49 / L1 79 with
// a 1:1 theoretical balance), i.e. barrier/latency bubbles, not throughput.
//   TRANSB=true : C[M,N] = A[M,K] * B[N,K]^T
//   TRANSB=false: C[M,N] = A[M,K] * B[K,N]
// Requires M % 128 == 0, K % 32 == 0; N guarded at float4 grain.
// ---------------------------------------------------------------------------
template<bool TRANSB>
__global__ void __launch_bounds__(128, 4)
sgemm_kernel(const float* __restrict__ Ag, const float* __restrict__ Bg,
             float* __restrict__ Cg,
             const float* __restrict__ addsrc, const float* __restrict__ bias,
             int M, int N, int K, int lda, int ldb, int ldc,
             long long sA1, long long sA2, long long sB1, long long sB2,
             long long sC1, long long sC2, int bdiv,
             int relu)
{
    int z  = blockIdx.z;
    int z1 = z / bdiv, z2 = z - z1 * bdiv;
    const float* A = Ag + z1 * sA1 + z2 * sA2;
    const float* B = Bg + z1 * sB1 + z2 * sB2;
    float*       C = Cg + z1 * sC1 + z2 * sC2;
    const float* add = addsrc ? (addsrc + z1 * sC1 + z2 * sC2) : (const float*)0;

    __shared__ float As[32][128];
    __shared__ float Bs[32][64];

    int m0 = blockIdx.y * 128;
    int n0 = blockIdx.x * 64;
    int t  = threadIdx.x;          // 128 threads
    int tx = t & 7, ty = t >> 3;   // fragment grid

    float acc[8][8];
    #pragma unroll
    for (int i = 0; i < 8; i++)
        #pragma unroll
        for (int j = 0; j < 8; j++) acc[i][j] = 0.f;

    for (int k0 = 0; k0 < K; k0 += 32) {
        // ---- A tile: thread t owns row m0+t, k-strip of 32 (8x float4).
        //      Stores As[k][t]: warp lanes hit 32 distinct banks. ----
        {
            const float* ap = A + (long long)(m0 + t) * lda + k0;
            #pragma unroll
            for (int r = 0; r < 8; r++) {
                float4 a4 = *(const float4*)(ap + r * 4);
                As[r*4+0][t] = a4.x;
                As[r*4+1][t] = a4.y;
                As[r*4+2][t] = a4.z;
                As[r*4+3][t] = a4.w;
            }
        }
        // ---- B tile ----
        if (TRANSB) {
            // 64 rows x 32 k = 512 float4: n = i&63 (32 distinct banks/warp)
            #pragma unroll
            for (int r = 0; r < 4; r++) {
                int i  = t + r * 128;
                int n  = i & 63, kq = i >> 6;
                float4 b4 = make_float4(0.f, 0.f, 0.f, 0.f);
                if (n0 + n < N)
                    b4 = *(const float4*)(B + (long long)(n0 + n) * ldb + (k0 + kq * 4));
                Bs[kq*4+0][n] = b4.x;
                Bs[kq*4+1][n] = b4.y;
                Bs[kq*4+2][n] = b4.z;
                Bs[kq*4+3][n] = b4.w;
            }
        } else {
            // k-major: contiguous float4 stores, conflict-free
            #pragma unroll
            for (int r = 0; r < 4; r++) {
                int i  = t + r * 128;
                int rk = i >> 4, nq = i & 15;
                float4 b4 = make_float4(0.f, 0.f, 0.f, 0.f);
                if (n0 + nq * 4 < N)
                    b4 = *(const float4*)(B + (long long)(k0 + rk) * ldb + (n0 + nq * 4));
                *(float4*)&Bs[rk][nq * 4] = b4;
            }
        }
        __syncthreads();
        #pragma unroll
        for (int k = 0; k < 32; k++) {
            float a[8], b[8];
            *(float4*)&a[0] = *(const float4*)&As[k][ty * 8];
            *(float4*)&a[4] = *(const float4*)&As[k][ty * 8 + 4];
            *(float4*)&b[0] = *(const float4*)&Bs[k][tx * 4];        // n = tx*4 + j
            *(float4*)&b[4] = *(const float4*)&Bs[k][tx * 4 + 32];   // n = 32 + tx*4 + j
            #pragma unroll
            for (int i = 0; i < 8; i++)
                #pragma unroll
                for (int j = 0; j < 8; j++)
                    acc[i][j] += a[i] * b[j];   // FFMA, strict k order
        }
        __syncthreads();
    }

    // ---- epilogue: 8 rows x 2 float4 per thread (split columns) ----
    #pragma unroll
    for (int i = 0; i < 8; i++) {
        long long m = m0 + ty * 8 + i;
        #pragma unroll
        for (int q = 0; q < 2; q++) {
            int n = n0 + q * 32 + tx * 4;
            if (n < N) {
                float4 r;
                r.x = acc[i][q*4+0]; r.y = acc[i][q*4+1];
                r.z = acc[i][q*4+2]; r.w = acc[i][q*4+3];
                if (bias) {
                    r.x = __fadd_rn(r.x, bias[n]);   r.y = __fadd_rn(r.y, bias[n+1]);
                    r.z = __fadd_rn(r.z, bias[n+2]); r.w = __fadd_rn(r.w, bias[n+3]);
                }
                if (add) {
                    float4 a4 = *(const float4*)(add + m * ldc + n);
                    r.x = __fadd_rn(r.x, a4.x); r.y = __fadd_rn(r.y, a4.y);
                    r.z = __fadd_rn(r.z, a4.z); r.w = __fadd_rn(r.w, a4.w);
                }
                if (relu) {
                    r.x = fmaxf(r.x, 0.f); r.y = fmaxf(r.y, 0.f);
                    r.z = fmaxf(r.z, 0.f); r.w = fmaxf(r.w, 0.f);
                }
                *(float4*)(C + m * ldc + n) = r;
            }
        }
    }
}

// ---------------------------------------------------------------------------
// Row softmax over 512 (non-causal), in place. One block (128 thr) per row.
// IEEE div by sqrt(96), libdevice expf, IEEE normalize. BIT-PATH LOAD-BEARING.
// ---------------------------------------------------------------------------
__global__ void softmax512_kernel(float* __restrict__ sc)
{
    long long row = blockIdx.x;
    float* p = sc + row * 512;
    int t = threadIdx.x;
    float v[4];
    #pragma unroll
    for (int i = 0; i < 4; i++) v[i] = __fdiv_rn(p[t + i * 128], SQRT_HD);
    float m = fmaxf(fmaxf(v[0], v[1]), fmaxf(v[2], v[3]));
    __shared__ float sm[4], ss[4];
    #pragma unroll
    for (int o = 16; o; o >>= 1) m = fmaxf(m, __shfl_xor_sync(0xffffffffu, m, o));
    if ((t & 31) == 0) sm[t >> 5] = m;
    __syncthreads();
    m = fmaxf(fmaxf(sm[0], sm[1]), fmaxf(sm[2], sm[3]));
    float s = 0.f;
    #pragma unroll
    for (int i = 0; i < 4; i++) { v[i] = expf(__fsub_rn(v[i], m)); s += v[i]; }
    #pragma unroll
    for (int o = 16; o; o >>= 1) s += __shfl_xor_sync(0xffffffffu, s, o);
    if ((t & 31) == 0) ss[t >> 5] = s;
    __syncthreads();
    s = ss[0] + ss[1] + ss[2] + ss[3];
    #pragma unroll
    for (int i = 0; i < 4; i++) p[t + i * 128] = __fdiv_rn(v[i], s);
}

// ---------------------------------------------------------------------------
// Tiny causal attention over depth (D=8 tokens), reading the fused qkv
// buffer (row stride QS, q at +0, k at +768, v at +1536).
// ---------------------------------------------------------------------------
__global__ void attn2_kernel(const float* __restrict__ qkv, float* __restrict__ o)
{
    int bl = blockIdx.x;   // 0..2047 = b*512+l
    int h  = blockIdx.y;   // 0..7
    int t  = threadIdx.x;  // 128
    __shared__ float qs[8][97], ks[8][97], vs[8][97], ps[8][8];
    long long qbase = (long long)bl * 8 * QS + h * HD;
    long long obase = (long long)bl * 8 * Hh + h * HD;
    if (t < 96) {
        #pragma unroll
        for (int tok = 0; tok < 8; tok++) {
            qs[tok][t] = qkv[qbase + tok * QS + t];
            ks[tok][t] = qkv[qbase + 768 + tok * QS + t];
            vs[tok][t] = qkv[qbase + 1536 + tok * QS + t];
        }
    }
    __syncthreads();
    if (t < 64) {
        int t1 = t >> 3, t2 = t & 7;
        float s = -1e30f;
        if (t2 <= t1) {
            float a = 0.f;
            #pragma unroll 8
            for (int d2 = 0; d2 < 96; d2++) a += qs[t1][d2] * ks[t2][d2];  // FFMA, d ascending
            s = __fdiv_rn(a, SQRT_HD);
        }
        float m = s;
        #pragma unroll
        for (int o2 = 1; o2 <= 4; o2 <<= 1) m = fmaxf(m, __shfl_xor_sync(0xffffffffu, m, o2));
        float e = (t2 <= t1) ? expf(__fsub_rn(s, m)) : 0.0f;
        float sum = e;
        #pragma unroll
        for (int o2 = 1; o2 <= 4; o2 <<= 1) sum += __shfl_xor_sync(0xffffffffu, sum, o2);
        ps[t1][t2] = __fdiv_rn(e, sum);
    }
    __syncthreads();
    if (t < 96) {
        #pragma unroll
        for (int t1 = 0; t1 < 8; t1++) {
            float a = 0.f;
            #pragma unroll
            for (int t2 = 0; t2 < 8; t2++) a += ps[t1][t2] * vs[t2][t];    // FFMA, m ascending
            o[obase + t1 * Hh + t] = a;
        }
    }
}

// ---------------------------------------------------------------------------
// Layout permutes: (B,D,L,H) <-> (B,L,D,H)
// ---------------------------------------------------------------------------
__global__ void perm_fwd_kernel(const float* __restrict__ in, float* __restrict__ out)
{
    long long i = (long long)blockIdx.x * 256 + threadIdx.x;
    if (i >= NTOT) return;
    int h = (int)(i % Hh);
    long long r = i / Hh;
    int l = (int)(r % Ll);
    long long bd = r / Ll;
    int dd = (int)(bd % Dd);
    int b  = (int)(bd / Dd);
    out[((long long)(b * Ll + l) * Dd + dd) * Hh + h] = in[i];
}

__global__ void perm_bwd_kernel(const float* __restrict__ in, float* __restrict__ out)
{
    long long i = (long long)blockIdx.x * 256 + threadIdx.x;
    if (i >= NTOT) return;
    int h = (int)(i % Hh);
    long long r = i / Hh;
    int l = (int)(r % Ll);
    long long bd = r / Ll;
    int dd = (int)(bd % Dd);
    int b  = (int)(bd / Dd);
    out[i] = in[((long long)(b * Ll + l) * Dd + dd) * Hh + h];
}

// ---------------------------------------------------------------------------
// Dictionary transpose: (768,4096) -> (4096,768)
// ---------------------------------------------------------------------------
__global__ void transpose_dict_kernel(const float* __restrict__ in, float* __restrict__ out)
{
    __shared__ float tile[32][33];
    int bx = blockIdx.x * 32;   // F dir
    int by = blockIdx.y * 32;   // H dir
    int x = threadIdx.x, y = threadIdx.y;
    #pragma unroll
    for (int j = 0; j < 32; j += 8)
        tile[y + j][x] = in[(long long)(by + y + j) * Ff + bx + x];
    __syncthreads();
    #pragma unroll
    for (int j = 0; j < 32; j += 8)
        out[(long long)(bx + y + j) * Hh + by + x] = tile[x][y + j];
}

// ---------------------------------------------------------------------------
// residual = x[:,1:] - x[:,:-1]  (row-major (B,7,L,H))
// ---------------------------------------------------------------------------
__global__ void res_kernel(const float* __restrict__ x, float* __restrict__ res)
{
    long long i = (long long)blockIdx.x * 256 + threadIdx.x;
    if (i >= RES_TOT) return;
    int h = (int)(i % Hh);
    long long r = i / Hh;
    int l = (int)(r % Ll);
    long long bd = r / Ll;
    int dd = (int)(bd % 7);
    int b  = (int)(bd / 7);
    long long i0 = ((long long)(b * Dd + dd) * Ll + l) * Hh + h;
    res[i] = __fsub_rn(x[i0 + (long long)Ll * Hh], x[i0]);
}

// ---------------------------------------------------------------------------
// Top-64 per row of 4096 via 4-pass radix select on the (monotone, >=0)
// float bit patterns. Selection set is IDENTICAL to iterative argmax with
// jax.lax.top_k tie semantics: all values > T, plus the lowest-index values
// == T to fill 64. Deterministic index-ascending compaction for (idx,val).
// Writes z_n directly into d_out + per-row L1 sum.
// ---------------------------------------------------------------------------
__global__ void topk_kernel(const float* __restrict__ z, float* __restrict__ out,
                            int* __restrict__ tki, float* __restrict__ tkv,
                            float* __restrict__ sparse_part)
{
    long long row = blockIdx.x;
    const float* zr = z + row * Ff;
    __shared__ float rS[Ff];
    __shared__ unsigned char sS[Ff];
    __shared__ int hist[256];
    __shared__ int tmp[256];
    __shared__ unsigned int sPrefix;
    __shared__ int sRem, sB, sRemNext;
    int t = threadIdx.x;          // 256 threads

    for (int i = t; i < Ff; i += 256) rS[i] = zr[i];
    if (t == 0) { sPrefix = 0u; sRem = TOPK; }
    __syncthreads();

    // ---- 4-pass radix select: find bit pattern of the 64th-largest ----
    #pragma unroll
    for (int shift = 24; shift >= 0; shift -= 8) {
        hist[t] = 0;
        __syncthreads();
        unsigned int mask = (shift == 24) ? 0u : (0xFFFFFFFFu << (shift + 8));
        unsigned int pfx  = sPrefix;
        for (int i = t; i < Ff; i += 256) {
            unsigned int u = __float_as_uint(rS[i]);
            if ((u & mask) == pfx) atomicAdd(&hist[(u >> shift) & 255], 1);
        }
        __syncthreads();
        // suffix sums: incl[t] = sum_{b >= 255-t} hist[b]
        int v = hist[255 - t];
        tmp[t] = v;
        __syncthreads();
        for (int off = 1; off < 256; off <<= 1) {
            int x = (t >= off) ? tmp[t - off] : 0;
            __syncthreads();
            tmp[t] += x;
            __syncthreads();
        }
        int rem  = sRem;
        int sfx  = tmp[t];                       // suffix(255-t)
        int sfx1 = (t == 0) ? 0 : tmp[t - 1];    // suffix(255-t+1)
        if (sfx >= rem && sfx1 < rem) {          // unique crossing thread
            sB = 255 - t;
            sRemNext = rem - sfx1;
        }
        __syncthreads();
        if (t == 0) {
            sPrefix |= ((unsigned int)sB) << shift;
            sRem = sRemNext;
        }
        __syncthreads();
    }
    unsigned int T = sPrefix;   // bits of 64th-largest value
    int rtake = sRem;           // # of ==T elements to take (lowest index first)

    // ---- blocked selection: thread t owns indices [16t, 16t+16) ----
    int base = t * 16;
    int cntEq = 0;
    #pragma unroll
    for (int j = 0; j < 16; j++)
        if (__float_as_uint(rS[base + j]) == T) cntEq++;
    // exclusive scan of equal-counts (deterministic ascending-index ranks)
    __syncthreads();
    tmp[t] = cntEq;
    __syncthreads();
    for (int off = 1; off < 256; off <<= 1) {
        int x = (t >= off) ? tmp[t - off] : 0;
        __syncthreads();
        tmp[t] += x;
        __syncthreads();
    }
    int eqRank = tmp[t] - cntEq;
    int cntSel = 0;
    #pragma unroll
    for (int j = 0; j < 16; j++) {
        unsigned int u = __float_as_uint(rS[base + j]);
        bool sel;
        if (u > T)       sel = true;
        else if (u == T) { sel = (eqRank < rtake); eqRank++; }
        else             sel = false;
        sS[base + j] = sel ? 1 : 0;
        cntSel += sel ? 1 : 0;
    }
    // exclusive scan of selected-counts -> compaction positions
    __syncthreads();
    tmp[t] = cntSel;
    __syncthreads();
    for (int off = 1; off < 256; off <<= 1) {
        int x = (t >= off) ? tmp[t - off] : 0;
        __syncthreads();
        tmp[t] += x;
        __syncthreads();
    }
    int pos = tmp[t] - cntSel;
    #pragma unroll
    for (int j = 0; j < 16; j++) {
        if (sS[base + j]) {
            tki[row * TOPK + pos] = base + j;
            tkv[row * TOPK + pos] = rS[base + j];
            pos++;
        }
    }
    __syncthreads();

    // ---- emit full z row + per-row L1 partial (deterministic) ----
    float ls = 0.f;
    long long ob = O_Z + row * Ff;
    for (int i = t; i < Ff; i += 256) {
        float vv = sS[i] ? rS[i] : 0.0f;
        out[ob + i] = vv;
        ls += vv;
    }
    __shared__ float sp[8];
    #pragma unroll
    for (int o = 16; o; o >>= 1) ls += __shfl_xor_sync(0xffffffffu, ls, o);
    if ((t & 31) == 0) sp[t >> 5] = ls;
    __syncthreads();
    if (t == 0) {
        float s = 0.f;
        #pragma unroll
        for (int w = 0; w < 8; w++) s += sp[w];
        sparse_part[row] = s;
    }
}

// ---------------------------------------------------------------------------
// Sparse decode: x_novel = sum_j z_j * dictT[j], fused with x_hat and
// per-row pred/recon loss partials. Block per row (256 threads, 3 dims each).
// ---------------------------------------------------------------------------
__global__ void novel_kernel(const float* __restrict__ dictT, const float* __restrict__ x,
                             const int* __restrict__ tki, const float* __restrict__ tkv,
                             float* __restrict__ out,
                             float* __restrict__ pred_part, float* __restrict__ recon_part)
{
    long long row = blockIdx.x;     // (b*7+dd)*512 + l
    int t = threadIdx.x;
    __shared__ int   sI[TOPK];
    __shared__ float sV[TOPK];
    if (t < TOPK) { sI[t] = tki[row * TOPK + t]; sV[t] = tkv[row * TOPK + t]; }
    __syncthreads();

    int l = (int)(row % Ll);
    long long bd = row / Ll;
    int dd = (int)(bd % 7);
    int b  = (int)(bd / 7);
    const float* xp = x + ((long long)(b * Dd + dd)     * Ll + l) * Hh;
    const float* xt = x + ((long long)(b * Dd + dd + 1) * Ll + l) * Hh;

    float a0 = 0.f, a1 = 0.f, a2 = 0.f;
    #pragma unroll 4
    for (int j = 0; j < TOPK; j++) {
        float vv = sV[j];
        const float* dr = dictT + (long long)sI[j] * Hh;
        a0 += vv * dr[t];
        a1 += vv * dr[t + 256];
        a2 += vv * dr[t + 512];
    }

    float lr = 0.f, lp = 0.f;
    long long ob = row * Hh;
    float nv[3] = { a0, a1, a2 };
    #pragma unroll
    for (int i = 0; i < 3; i++) {
        int h = t + i * 256;
        float px = xp[h], tg = xt[h];
        float nov = nv[i];
        float xh = __fadd_rn(px, nov);
        out[O_NOVEL + ob + h] = nov;
        out[O_XHAT  + ob + h] = xh;
        float d1 = __fsub_rn(xh, tg); lr += d1 * d1;
        float d2 = __fsub_rn(tg, px); lp += d2 * d2;
    }
    __shared__ float s1[8], s2[8];
    #pragma unroll
    for (int o = 16; o; o >>= 1) {
        lr += __shfl_xor_sync(0xffffffffu, lr, o);
        lp += __shfl_xor_sync(0xffffffffu, lp, o);
    }
    if ((t & 31) == 0) { s1[t >> 5] = lr; s2[t >> 5] = lp; }
    __syncthreads();
    if (t == 0) {
        float r = 0.f, p = 0.f;
        #pragma unroll
        for (int w = 0; w < 8; w++) { r += s1[w]; p += s2[w]; }
        recon_part[row] = r;
        pred_part[row]  = p;
    }
}

// ---------------------------------------------------------------------------
// Final deterministic loss reduction
// ---------------------------------------------------------------------------
__global__ void loss_kernel(const float* __restrict__ pred_part,
                            const float* __restrict__ recon_part,
                            const float* __restrict__ sparse_part,
                            float* __restrict__ out)
{
    int t = threadIdx.x;   // 256
    double sp = 0.0, sr = 0.0, ss = 0.0;
    for (int i = t; i < RES_ROWS; i += 256) {
        sp += (double)pred_part[i];
        sr += (double)recon_part[i];
        ss += (double)sparse_part[i];
    }
    __shared__ double da[256], db[256], dc[256];
    da[t] = sp; db[t] = sr; dc[t] = ss;
    __syncthreads();
    for (int o = 128; o; o >>= 1) {
        if (t < o) { da[t] += da[t + o]; db[t] += db[t + o]; dc[t] += dc[t + o]; }
        __syncthreads();
    }
    if (t == 0) {
        double loss = da[0] / 11010048.0 + db[0] / 11010048.0 + 0.001 * (dc[0] / 58720256.0);
        out[O_LOSS] = (float)loss;
    }
}

// ---------------------------------------------------------------------------
// Host side
// ---------------------------------------------------------------------------
static void sgemm(bool transB, const float* A, const float* B, float* C,
                  const float* add, const float* bias,
                  int M, int N, int K, int lda, int ldb, int ldc,
                  long long sA1, long long sA2, long long sB1, long long sB2,
                  long long sC1, long long sC2, int bdiv, int batch,
                  int relu)
{
    dim3 grid((N + 63) / 64, M / 128, batch);
    if (transB)
        sgemm_kernel<true><<<grid, 128>>>(A, B, C, add, bias, M, N, K, lda, ldb, ldc,
                                          sA1, sA2, sB1, sB2, sC1, sC2, bdiv, relu);
    else
        sgemm_kernel<false><<<grid, 128>>>(A, B, C, add, bias, M, N, K, lda, ldb, ldc,
                                           sA1, sA2, sB1, sB2, sC1, sC2, bdiv, relu);
}

extern "C" void kernel_launch(void* const* d_in, const int* in_sizes, int n_in,
                              void* d_out, int out_size)
{
    const float* zL    = (const float*)d_in[0];
    const float* Wq_l  = (const float*)d_in[1];
    const float* Wk_l  = (const float*)d_in[2];
    const float* Wv_l  = (const float*)d_in[3];
    const float* Wo_l  = (const float*)d_in[4];
    const float* gl    = (const float*)d_in[5];
    const float* bl    = (const float*)d_in[6];
    const float* Wq_d  = (const float*)d_in[7];
    const float* Wk_d  = (const float*)d_in[8];
    const float* Wv_d  = (const float*)d_in[9];
    const float* Wo_d  = (const float*)d_in[10];
    const float* gd    = (const float*)d_in[11];
    const float* bd    = (const float*)d_in[12];
    const float* dict  = (const float*)d_in[13];
    const float* biasn = (const float*)d_in[14];
    float* out = (float*)d_out;

    float *p_ln, *p_qkv, *p_wcat, *p_attn, *p_x, *p_xt, *p_sc, *p_res, *p_z, *p_dT, *p_tkv, *p_part;
    int *p_tki;
    cudaGetSymbolAddress((void**)&p_ln,   g_ln);
    cudaGetSymbolAddress((void**)&p_qkv,  g_qkv);
    cudaGetSymbolAddress((void**)&p_wcat, g_wcat);
    cudaGetSymbolAddress((void**)&p_attn, g_attn);
    cudaGetSymbolAddress((void**)&p_x,    g_x);
    cudaGetSymbolAddress((void**)&p_xt,   g_xt);
    cudaGetSymbolAddress((void**)&p_sc,   g_sc);
    cudaGetSymbolAddress((void**)&p_res,  g_res);
    cudaGetSymbolAddress((void**)&p_z,    g_z);
    cudaGetSymbolAddress((void**)&p_dT,   g_dictT);
    cudaGetSymbolAddress((void**)&p_tki,  g_tki);
    cudaGetSymbolAddress((void**)&p_tkv,  g_tkv);
    cudaGetSymbolAddress((void**)&p_part, g_part);

    const long long SQH  = (long long)Ll * Hh;   // 512*768 seq stride (attn buf)
    const long long SQQ  = (long long)Ll * QS;   // 512*2304 seq stride (qkv buf)
    const long long SCB  = (long long)Ll * Ll;   // per-head score size
    const size_t WBYTES  = (size_t)Hh * Hh * sizeof(float);

    // ---------------- Stage A: attention over L (non-causal) ----------------
    ln_kernel<<<ROWS, 256>>>(zL, p_ln, gl, bl);
    // concat Wq|Wk|Wv and run one fused projection GEMM (N=2304)
    cudaMemcpyAsync(p_wcat,             Wq_l, WBYTES, cudaMemcpyDeviceToDevice);
    cudaMemcpyAsync(p_wcat + Hh * Hh,   Wk_l, WBYTES, cudaMemcpyDeviceToDevice);
    cudaMemcpyAsync(p_wcat + 2*Hh*Hh,   Wv_l, WBYTES, cudaMemcpyDeviceToDevice);
    sgemm(true, p_ln, p_wcat, p_qkv, 0, 0, ROWS, QS, Hh, Hh, Hh, QS,
          0,0,0,0,0,0, 1, 1, 0);
    // raw scores[seq,head] = Q K^T (scaling done in softmax with IEEE div)
    sgemm(true, p_qkv, p_qkv + 768, p_sc, 0, 0, Ll, Ll, HD, QS, QS, Ll,
          SQQ, HD, SQQ, HD, 8*SCB, SCB, NHEAD, 32*NHEAD, 0);
    softmax512_kernel<<<131072, 128>>>(p_sc);
    // attn = P V
    sgemm(false, p_sc, p_qkv + 1536, p_attn, 0, 0, Ll, HD, Ll, Ll, QS, Hh,
          8*SCB, SCB, SQQ, HD, SQH, HD, NHEAD, 32*NHEAD, 0);
    // x = zL + attn Wo^T
    sgemm(true, p_attn, Wo_l, p_x, zL, 0, ROWS, Hh, Hh, Hh, Hh, Hh,
          0,0,0,0,0,0, 1, 1, 0);

    // ---------------- Stage B: causal attention over depth D ----------------
    perm_fwd_kernel<<<49152, 256>>>(p_x, p_xt);
    ln_kernel<<<ROWS, 256>>>(p_xt, p_ln, gd, bd);
    cudaMemcpyAsync(p_wcat,             Wq_d, WBYTES, cudaMemcpyDeviceToDevice);
    cudaMemcpyAsync(p_wcat + Hh * Hh,   Wk_d, WBYTES, cudaMemcpyDeviceToDevice);
    cudaMemcpyAsync(p_wcat + 2*Hh*Hh,   Wv_d, WBYTES, cudaMemcpyDeviceToDevice);
    sgemm(true, p_ln, p_wcat, p_qkv, 0, 0, ROWS, QS, Hh, Hh, Hh, QS,
          0,0,0,0,0,0, 1, 1, 0);
    attn2_kernel<<<dim3(2048, NHEAD), 128>>>(p_qkv, p_attn);
    sgemm(true, p_attn, Wo_d, p_xt, p_xt, 0, ROWS, Hh, Hh, Hh, Hh, Hh,
          0,0,0,0,0,0, 1, 1, 0);
    perm_bwd_kernel<<<49152, 256>>>(p_xt, p_x);

    // ---------------- SAE head ----------------
    transpose_dict_kernel<<<dim3(128, 24), dim3(32, 8)>>>(dict, p_dT);
    res_kernel<<<43008, 256>>>(p_x, p_res);
    // z_dense = relu(res @ dict + bias)   (strict k-seq FMA -> correlates with ref)
    sgemm(false, p_res, dict, p_z, 0, biasn, RES_ROWS, Ff, Hh, Hh, Ff, Ff,
          0,0,0,0,0,0, 1, 1, 1);
    topk_kernel<<<RES_ROWS, 256>>>(p_z, out, p_tki, p_tkv, p_part + 2 * RES_ROWS);
    novel_kernel<<<RES_ROWS, 256>>>(p_dT, p_x, p_tki, p_tkv, out,
                                    p_part, p_part + RES_ROWS);
    loss_kernel<<<1, 256>>>(p_part, p_part + RES_ROWS, p_part + 2 * RES_ROWS, out);
}

// round 15
// speedup vs baseline: 1.3159x; 1.0517x over previous
#include <cuda_runtime.h>
#include <cuda_bf16.h>
#include <math.h>

// ---------------------------------------------------------------------------
// Problem constants
// ---------------------------------------------------------------------------
#define Bsz   4
#define Dd    8
#define Ll    512
#define Hh    768
#define Ff    4096
#define NHEAD 8
#define HD    96         // head dim
#define TOPK  64
#define ROWS  16384      // B*D*L rows of H
#define QS    2304       // fused q|k|v row stride
#define NTOT  12582912LL // 16384*768
#define RES_ROWS 14336   // B*(D-1)*L
#define RES_TOT  11010048LL  // 14336*768
#define Z_TOT    58720256LL  // 14336*4096

#define O_LOSS  0LL
#define O_XHAT  1LL
#define O_NOVEL 11010049LL   // 1 + 11010048
#define O_Z     22020097LL   // 1 + 2*11010048

#define SQRT_HD 9.79795897113271239f   // fp32(sqrt(96)), == sqrtf(96.0f)

// row remap (B,L,D) -> (B,D,L): m = (b*512+l)*8+dd  ->  (b*8+dd)*512+l
__device__ __forceinline__ int permrow(int m)
{
    int b  = m >> 12;          // m / 4096
    int r  = m & 4095;
    int l  = r >> 3;
    int dd = r & 7;
    return (b << 12) | (dd << 9) | l;
}

// ---------------------------------------------------------------------------
// Static device workspace (allocation-free rule: __device__ globals)
// ---------------------------------------------------------------------------
__device__ float g_ln  [NTOT];
__device__ float g_qkv [16384 * 2304];   // fused q|k|v, 151 MB
__device__ float g_wcat[3 * Hh * Hh];    // concatenated Wq|Wk|Wv
__device__ float g_attn[NTOT];
__device__ float g_x   [NTOT];
__device__ float g_sc  [67108864];       // 256 * 512 * 512 scores
__device__ float g_res [RES_TOT];
__device__ float g_z   [Z_TOT];
__device__ float g_dictT[Ff * Hh];
__device__ int   g_tki [RES_ROWS * TOPK];
__device__ float g_tkv [RES_ROWS * TOPK];
__device__ float g_part[3 * RES_ROWS];   // pred | recon | sparse partials

// ---------------------------------------------------------------------------
// LayerNorm: one block per row of 768, 256 threads. Two-pass variance
// (reference's literal mean(square(x - mu))), libdevice rsqrtf, IEEE
// divisions, NO fma contraction in the epilogue. BIT-PATH IS LOAD-BEARING.
// permIn=1: output row r reads source row permrow(r) (replaces perm_fwd).
// ---------------------------------------------------------------------------
__global__ void ln_kernel(const float* __restrict__ x, float* __restrict__ y,
                          const float* __restrict__ gg, const float* __restrict__ bb,
                          int permIn)
{
    int orow = blockIdx.x;
    long long srow = permIn ? permrow(orow) : orow;
    const float* xr = x + srow * (long long)Hh;
    float* yr = y + (long long)orow * Hh;
    int t = threadIdx.x;
    float v0 = xr[t], v1 = xr[t + 256], v2 = xr[t + 512];
    __shared__ float sa[8], sq[8];

    float s = __fadd_rn(__fadd_rn(v0, v1), v2);
    #pragma unroll
    for (int o = 16; o; o >>= 1) s += __shfl_xor_sync(0xffffffffu, s, o);
    if ((t & 31) == 0) sa[t >> 5] = s;
    __syncthreads();
    s = 0.f;
    #pragma unroll
    for (int w = 0; w < 8; w++) s += sa[w];
    float mu = __fdiv_rn(s, 768.0f);

    float d0 = __fsub_rn(v0, mu), d1 = __fsub_rn(v1, mu), d2 = __fsub_rn(v2, mu);
    float s2 = __fadd_rn(__fadd_rn(__fmul_rn(d0, d0), __fmul_rn(d1, d1)), __fmul_rn(d2, d2));
    #pragma unroll
    for (int o = 16; o; o >>= 1) s2 += __shfl_xor_sync(0xffffffffu, s2, o);
    if ((t & 31) == 0) sq[t >> 5] = s2;
    __syncthreads();
    s2 = 0.f;
    #pragma unroll
    for (int w = 0; w < 8; w++) s2 += sq[w];
    float var  = __fdiv_rn(s2, 768.0f);
    float rstd = rsqrtf(__fadd_rn(var, 1e-5f));

    yr[t]       = __fadd_rn(__fmul_rn(__fmul_rn(d0, rstd), gg[t]),       bb[t]);
    yr[t + 256] = __fadd_rn(__fmul_rn(__fmul_rn(d1, rstd), gg[t + 256]), bb[t + 256]);
    yr[t + 512] = __fadd_rn(__fmul_rn(__fmul_rn(d2, rstd), gg[t + 512]), bb[t + 512]);
}

// ---------------------------------------------------------------------------
// Tiled SGEMM, STRICT k-ascending fp32 FMA accumulation per output element.
// Per-element rounding chain identical to R9 (correlated with the reference
// GEMM — protects the top-k boundary). DO NOT alter the order.
//
// R15: BM=128, BN=64, BK template (64 for K%64==0, 32 for scores K=96),
// 128 threads, 8x8 fragment, conflict-free smem schedule. BK=64 halves the
// barrier count again (the R14-proven mechanism: sync-frequency bubbles).
// permRows=1: epilogue row-remaps BOTH the add-read and the C-write via
// permrow(m) — replaces perm_bwd with zero extra traffic.
//   TRANSB=true : C[M,N] = A[M,K] * B[N,K]^T
//   TRANSB=false: C[M,N] = A[M,K] * B[K,N]
// Requires M % 128 == 0, K % BK == 0; N guarded at float4 grain.
// ---------------------------------------------------------------------------
template<bool TRANSB, int BK>
__global__ void __launch_bounds__(128, 4)
sgemm_kernel(const float* __restrict__ Ag, const float* __restrict__ Bg,
             float* __restrict__ Cg,
             const float* __restrict__ addsrc, const float* __restrict__ bias,
             int M, int N, int K, int lda, int ldb, int ldc,
             long long sA1, long long sA2, long long sB1, long long sB2,
             long long sC1, long long sC2, int bdiv,
             int relu, int permRows)
{
    int z  = blockIdx.z;
    int z1 = z / bdiv, z2 = z - z1 * bdiv;
    const float* A = Ag + z1 * sA1 + z2 * sA2;
    const float* B = Bg + z1 * sB1 + z2 * sB2;
    float*       C = Cg + z1 * sC1 + z2 * sC2;
    const float* add = addsrc ? (addsrc + z1 * sC1 + z2 * sC2) : (const float*)0;

    __shared__ float As[BK][128];
    __shared__ float Bs[BK][64];

    int m0 = blockIdx.y * 128;
    int n0 = blockIdx.x * 64;
    int t  = threadIdx.x;          // 128 threads
    int tx = t & 7, ty = t >> 3;   // fragment grid

    float acc[8][8];
    #pragma unroll
    for (int i = 0; i < 8; i++)
        #pragma unroll
        for (int j = 0; j < 8; j++) acc[i][j] = 0.f;

    for (int k0 = 0; k0 < K; k0 += BK) {
        // ---- A tile: thread t owns row m0+t, k-strip of BK (BK/4 float4).
        //      Stores As[k][t]: warp lanes hit 32 distinct banks. ----
        {
            const float* ap = A + (long long)(m0 + t) * lda + k0;
            #pragma unroll
            for (int r = 0; r < BK / 4; r++) {
                float4 a4 = *(const float4*)(ap + r * 4);
                As[r*4+0][t] = a4.x;
                As[r*4+1][t] = a4.y;
                As[r*4+2][t] = a4.z;
                As[r*4+3][t] = a4.w;
            }
        }
        // ---- B tile ----
        if (TRANSB) {
            // 64 rows x BK k = 16*BK float4: n = i&63 (32 distinct banks/warp)
            #pragma unroll
            for (int r = 0; r < BK / 8; r++) {
                int i  = t + r * 128;
                int n  = i & 63, kq = i >> 6;
                float4 b4 = make_float4(0.f, 0.f, 0.f, 0.f);
                if (n0 + n < N)
                    b4 = *(const float4*)(B + (long long)(n0 + n) * ldb + (k0 + kq * 4));
                Bs[kq*4+0][n] = b4.x;
                Bs[kq*4+1][n] = b4.y;
                Bs[kq*4+2][n] = b4.z;
                Bs[kq*4+3][n] = b4.w;
            }
        } else {
            // k-major: contiguous float4 stores, conflict-free
            #pragma unroll
            for (int r = 0; r < BK / 8; r++) {
                int i  = t + r * 128;
                int rk = i >> 4, nq = i & 15;
                float4 b4 = make_float4(0.f, 0.f, 0.f, 0.f);
                if (n0 + nq * 4 < N)
                    b4 = *(const float4*)(B + (long long)(k0 + rk) * ldb + (n0 + nq * 4));
                *(float4*)&Bs[rk][nq * 4] = b4;
            }
        }
        __syncthreads();
        #pragma unroll 16
        for (int k = 0; k < BK; k++) {
            float a[8], b[8];
            *(float4*)&a[0] = *(const float4*)&As[k][ty * 8];
            *(float4*)&a[4] = *(const float4*)&As[k][ty * 8 + 4];
            *(float4*)&b[0] = *(const float4*)&Bs[k][tx * 4];        // n = tx*4 + j
            *(float4*)&b[4] = *(const float4*)&Bs[k][tx * 4 + 32];   // n = 32 + tx*4 + j
            #pragma unroll
            for (int i = 0; i < 8; i++)
                #pragma unroll
                for (int j = 0; j < 8; j++)
                    acc[i][j] += a[i] * b[j];   // FFMA, strict k order
        }
        __syncthreads();
    }

    // ---- epilogue: 8 rows x 2 float4 per thread (split columns) ----
    #pragma unroll
    for (int i = 0; i < 8; i++) {
        int  mi = m0 + ty * 8 + i;
        long long m = permRows ? permrow(mi) : mi;
        #pragma unroll
        for (int q = 0; q < 2; q++) {
            int n = n0 + q * 32 + tx * 4;
            if (n < N) {
                float4 r;
                r.x = acc[i][q*4+0]; r.y = acc[i][q*4+1];
                r.z = acc[i][q*4+2]; r.w = acc[i][q*4+3];
                if (bias) {
                    r.x = __fadd_rn(r.x, bias[n]);   r.y = __fadd_rn(r.y, bias[n+1]);
                    r.z = __fadd_rn(r.z, bias[n+2]); r.w = __fadd_rn(r.w, bias[n+3]);
                }
                if (add) {
                    float4 a4 = *(const float4*)(add + m * ldc + n);
                    r.x = __fadd_rn(r.x, a4.x); r.y = __fadd_rn(r.y, a4.y);
                    r.z = __fadd_rn(r.z, a4.z); r.w = __fadd_rn(r.w, a4.w);
                }
                if (relu) {
                    r.x = fmaxf(r.x, 0.f); r.y = fmaxf(r.y, 0.f);
                    r.z = fmaxf(r.z, 0.f); r.w = fmaxf(r.w, 0.f);
                }
                *(float4*)(C + m * ldc + n) = r;
            }
        }
    }
}

// ---------------------------------------------------------------------------
// Row softmax over 512 (non-causal), in place. One block (128 thr) per row.
// IEEE div by sqrt(96), libdevice expf, IEEE normalize. BIT-PATH LOAD-BEARING.
// ---------------------------------------------------------------------------
__global__ void softmax512_kernel(float* __restrict__ sc)
{
    long long row = blockIdx.x;
    float* p = sc + row * 512;
    int t = threadIdx.x;
    float v[4];
    #pragma unroll
    for (int i = 0; i < 4; i++) v[i] = __fdiv_rn(p[t + i * 128], SQRT_HD);
    float m = fmaxf(fmaxf(v[0], v[1]), fmaxf(v[2], v[3]));
    __shared__ float sm[4], ss[4];
    #pragma unroll
    for (int o = 16; o; o >>= 1) m = fmaxf(m, __shfl_xor_sync(0xffffffffu, m, o));
    if ((t & 31) == 0) sm[t >> 5] = m;
    __syncthreads();
    m = fmaxf(fmaxf(sm[0], sm[1]), fmaxf(sm[2], sm[3]));
    float s = 0.f;
    #pragma unroll
    for (int i = 0; i < 4; i++) { v[i] = expf(__fsub_rn(v[i], m)); s += v[i]; }
    #pragma unroll
    for (int o = 16; o; o >>= 1) s += __shfl_xor_sync(0xffffffffu, s, o);
    if ((t & 31) == 0) ss[t >> 5] = s;
    __syncthreads();
    s = ss[0] + ss[1] + ss[2] + ss[3];
    #pragma unroll
    for (int i = 0; i < 4; i++) p[t + i * 128] = __fdiv_rn(v[i], s);
}

// ---------------------------------------------------------------------------
// Tiny causal attention over depth (D=8 tokens), reading the fused qkv
// buffer (row stride QS, q at +0, k at +768, v at +1536).
// ---------------------------------------------------------------------------
__global__ void attn2_kernel(const float* __restrict__ qkv, float* __restrict__ o)
{
    int bl = blockIdx.x;   // 0..2047 = b*512+l
    int h  = blockIdx.y;   // 0..7
    int t  = threadIdx.x;  // 128
    __shared__ float qs[8][97], ks[8][97], vs[8][97], ps[8][8];
    long long qbase = (long long)bl * 8 * QS + h * HD;
    long long obase = (long long)bl * 8 * Hh + h * HD;
    if (t < 96) {
        #pragma unroll
        for (int tok = 0; tok < 8; tok++) {
            qs[tok][t] = qkv[qbase + tok * QS + t];
            ks[tok][t] = qkv[qbase + 768 + tok * QS + t];
            vs[tok][t] = qkv[qbase + 1536 + tok * QS + t];
        }
    }
    __syncthreads();
    if (t < 64) {
        int t1 = t >> 3, t2 = t & 7;
        float s = -1e30f;
        if (t2 <= t1) {
            float a = 0.f;
            #pragma unroll 8
            for (int d2 = 0; d2 < 96; d2++) a += qs[t1][d2] * ks[t2][d2];  // FFMA, d ascending
            s = __fdiv_rn(a, SQRT_HD);
        }
        float m = s;
        #pragma unroll
        for (int o2 = 1; o2 <= 4; o2 <<= 1) m = fmaxf(m, __shfl_xor_sync(0xffffffffu, m, o2));
        float e = (t2 <= t1) ? expf(__fsub_rn(s, m)) : 0.0f;
        float sum = e;
        #pragma unroll
        for (int o2 = 1; o2 <= 4; o2 <<= 1) sum += __shfl_xor_sync(0xffffffffu, sum, o2);
        ps[t1][t2] = __fdiv_rn(e, sum);
    }
    __syncthreads();
    if (t < 96) {
        #pragma unroll
        for (int t1 = 0; t1 < 8; t1++) {
            float a = 0.f;
            #pragma unroll
            for (int t2 = 0; t2 < 8; t2++) a += ps[t1][t2] * vs[t2][t];    // FFMA, m ascending
            o[obase + t1 * Hh + t] = a;
        }
    }
}

// ---------------------------------------------------------------------------
// Dictionary transpose: (768,4096) -> (4096,768)
// ---------------------------------------------------------------------------
__global__ void transpose_dict_kernel(const float* __restrict__ in, float* __restrict__ out)
{
    __shared__ float tile[32][33];
    int bx = blockIdx.x * 32;   // F dir
    int by = blockIdx.y * 32;   // H dir
    int x = threadIdx.x, y = threadIdx.y;
    #pragma unroll
    for (int j = 0; j < 32; j += 8)
        tile[y + j][x] = in[(long long)(by + y + j) * Ff + bx + x];
    __syncthreads();
    #pragma unroll
    for (int j = 0; j < 32; j += 8)
        out[(long long)(bx + y + j) * Hh + by + x] = tile[x][y + j];
}

// ---------------------------------------------------------------------------
// residual = x[:,1:] - x[:,:-1]  (row-major (B,7,L,H))
// ---------------------------------------------------------------------------
__global__ void res_kernel(const float* __restrict__ x, float* __restrict__ res)
{
    long long i = (long long)blockIdx.x * 256 + threadIdx.x;
    if (i >= RES_TOT) return;
    int h = (int)(i % Hh);
    long long r = i / Hh;
    int l = (int)(r % Ll);
    long long bd = r / Ll;
    int dd = (int)(bd % 7);
    int b  = (int)(bd / 7);
    long long i0 = ((long long)(b * Dd + dd) * Ll + l) * Hh + h;
    res[i] = __fsub_rn(x[i0 + (long long)Ll * Hh], x[i0]);
}

// ---------------------------------------------------------------------------
// Top-64 per row of 4096 via 4-pass radix select on the (monotone, >=0)
// float bit patterns. Selection set IDENTICAL to jax.lax.top_k semantics.
// Deterministic index-ascending compaction. Writes z_n into d_out + L1 sum.
// ---------------------------------------------------------------------------
__global__ void topk_kernel(const float* __restrict__ z, float* __restrict__ out,
                            int* __restrict__ tki, float* __restrict__ tkv,
                            float* __restrict__ sparse_part)
{
    long long row = blockIdx.x;
    const float* zr = z + row * Ff;
    __shared__ float rS[Ff];
    __shared__ unsigned char sS[Ff];
    __shared__ int hist[256];
    __shared__ int tmp[256];
    __shared__ unsigned int sPrefix;
    __shared__ int sRem, sB, sRemNext;
    int t = threadIdx.x;          // 256 threads

    for (int i = t; i < Ff; i += 256) rS[i] = zr[i];
    if (t == 0) { sPrefix = 0u; sRem = TOPK; }
    __syncthreads();

    #pragma unroll
    for (int shift = 24; shift >= 0; shift -= 8) {
        hist[t] = 0;
        __syncthreads();
        unsigned int mask = (shift == 24) ? 0u : (0xFFFFFFFFu << (shift + 8));
        unsigned int pfx  = sPrefix;
        for (int i = t; i < Ff; i += 256) {
            unsigned int u = __float_as_uint(rS[i]);
            if ((u & mask) == pfx) atomicAdd(&hist[(u >> shift) & 255], 1);
        }
        __syncthreads();
        int v = hist[255 - t];
        tmp[t] = v;
        __syncthreads();
        for (int off = 1; off < 256; off <<= 1) {
            int x = (t >= off) ? tmp[t - off] : 0;
            __syncthreads();
            tmp[t] += x;
            __syncthreads();
        }
        int rem  = sRem;
        int sfx  = tmp[t];
        int sfx1 = (t == 0) ? 0 : tmp[t - 1];
        if (sfx >= rem && sfx1 < rem) {
            sB = 255 - t;
            sRemNext = rem - sfx1;
        }
        __syncthreads();
        if (t == 0) {
            sPrefix |= ((unsigned int)sB) << shift;
            sRem = sRemNext;
        }
        __syncthreads();
    }
    unsigned int T = sPrefix;
    int rtake = sRem;

    int base = t * 16;
    int cntEq = 0;
    #pragma unroll
    for (int j = 0; j < 16; j++)
        if (__float_as_uint(rS[base + j]) == T) cntEq++;
    __syncthreads();
    tmp[t] = cntEq;
    __syncthreads();
    for (int off = 1; off < 256; off <<= 1) {
        int x = (t >= off) ? tmp[t - off] : 0;
        __syncthreads();
        tmp[t] += x;
        __syncthreads();
    }
    int eqRank = tmp[t] - cntEq;
    int cntSel = 0;
    #pragma unroll
    for (int j = 0; j < 16; j++) {
        unsigned int u = __float_as_uint(rS[base + j]);
        bool sel;
        if (u > T)       sel = true;
        else if (u == T) { sel = (eqRank < rtake); eqRank++; }
        else             sel = false;
        sS[base + j] = sel ? 1 : 0;
        cntSel += sel ? 1 : 0;
    }
    __syncthreads();
    tmp[t] = cntSel;
    __syncthreads();
    for (int off = 1; off < 256; off <<= 1) {
        int x = (t >= off) ? tmp[t - off] : 0;
        __syncthreads();
        tmp[t] += x;
        __syncthreads();
    }
    int pos = tmp[t] - cntSel;
    #pragma unroll
    for (int j = 0; j < 16; j++) {
        if (sS[base + j]) {
            tki[row * TOPK + pos] = base + j;
            tkv[row * TOPK + pos] = rS[base + j];
            pos++;
        }
    }
    __syncthreads();

    float ls = 0.f;
    long long ob = O_Z + row * Ff;
    for (int i = t; i < Ff; i += 256) {
        float vv = sS[i] ? rS[i] : 0.0f;
        out[ob + i] = vv;
        ls += vv;
    }
    __shared__ float sp[8];
    #pragma unroll
    for (int o = 16; o; o >>= 1) ls += __shfl_xor_sync(0xffffffffu, ls, o);
    if ((t & 31) == 0) sp[t >> 5] = ls;
    __syncthreads();
    if (t == 0) {
        float s = 0.f;
        #pragma unroll
        for (int w = 0; w < 8; w++) s += sp[w];
        sparse_part[row] = s;
    }
}

// ---------------------------------------------------------------------------
// Sparse decode: x_novel = sum_j z_j * dictT[j], fused with x_hat and
// per-row pred/recon loss partials. Block per row (256 threads, 3 dims each).
// ---------------------------------------------------------------------------
__global__ void novel_kernel(const float* __restrict__ dictT, const float* __restrict__ x,
                             const int* __restrict__ tki, const float* __restrict__ tkv,
                             float* __restrict__ out,
                             float* __restrict__ pred_part, float* __restrict__ recon_part)
{
    long long row = blockIdx.x;     // (b*7+dd)*512 + l
    int t = threadIdx.x;
    __shared__ int   sI[TOPK];
    __shared__ float sV[TOPK];
    if (t < TOPK) { sI[t] = tki[row * TOPK + t]; sV[t] = tkv[row * TOPK + t]; }
    __syncthreads();

    int l = (int)(row % Ll);
    long long bd = row / Ll;
    int dd = (int)(bd % 7);
    int b  = (int)(bd / 7);
    const float* xp = x + ((long long)(b * Dd + dd)     * Ll + l) * Hh;
    const float* xt = x + ((long long)(b * Dd + dd + 1) * Ll + l) * Hh;

    float a0 = 0.f, a1 = 0.f, a2 = 0.f;
    #pragma unroll 4
    for (int j = 0; j < TOPK; j++) {
        float vv = sV[j];
        const float* dr = dictT + (long long)sI[j] * Hh;
        a0 += vv * dr[t];
        a1 += vv * dr[t + 256];
        a2 += vv * dr[t + 512];
    }

    float lr = 0.f, lp = 0.f;
    long long ob = row * Hh;
    float nv[3] = { a0, a1, a2 };
    #pragma unroll
    for (int i = 0; i < 3; i++) {
        int h = t + i * 256;
        float px = xp[h], tg = xt[h];
        float nov = nv[i];
        float xh = __fadd_rn(px, nov);
        out[O_NOVEL + ob + h] = nov;
        out[O_XHAT  + ob + h] = xh;
        float d1 = __fsub_rn(xh, tg); lr += d1 * d1;
        float d2 = __fsub_rn(tg, px); lp += d2 * d2;
    }
    __shared__ float s1[8], s2[8];
    #pragma unroll
    for (int o = 16; o; o >>= 1) {
        lr += __shfl_xor_sync(0xffffffffu, lr, o);
        lp += __shfl_xor_sync(0xffffffffu, lp, o);
    }
    if ((t & 31) == 0) { s1[t >> 5] = lr; s2[t >> 5] = lp; }
    __syncthreads();
    if (t == 0) {
        float r = 0.f, p = 0.f;
        #pragma unroll
        for (int w = 0; w < 8; w++) { r += s1[w]; p += s2[w]; }
        recon_part[row] = r;
        pred_part[row]  = p;
    }
}

// ---------------------------------------------------------------------------
// Final deterministic loss reduction
// ---------------------------------------------------------------------------
__global__ void loss_kernel(const float* __restrict__ pred_part,
                            const float* __restrict__ recon_part,
                            const float* __restrict__ sparse_part,
                            float* __restrict__ out)
{
    int t = threadIdx.x;   // 256
    double sp = 0.0, sr = 0.0, ss = 0.0;
    for (int i = t; i < RES_ROWS; i += 256) {
        sp += (double)pred_part[i];
        sr += (double)recon_part[i];
        ss += (double)sparse_part[i];
    }
    __shared__ double da[256], db[256], dc[256];
    da[t] = sp; db[t] = sr; dc[t] = ss;
    __syncthreads();
    for (int o = 128; o; o >>= 1) {
        if (t < o) { da[t] += da[t + o]; db[t] += db[t + o]; dc[t] += dc[t + o]; }
        __syncthreads();
    }
    if (t == 0) {
        double loss = da[0] / 11010048.0 + db[0] / 11010048.0 + 0.001 * (dc[0] / 58720256.0);
        out[O_LOSS] = (float)loss;
    }
}

// ---------------------------------------------------------------------------
// Host side
// ---------------------------------------------------------------------------
static void sgemm(bool transB, int bk64, const float* A, const float* B, float* C,
                  const float* add, const float* bias,
                  int M, int N, int K, int lda, int ldb, int ldc,
                  long long sA1, long long sA2, long long sB1, long long sB2,
                  long long sC1, long long sC2, int bdiv, int batch,
                  int relu, int permRows)
{
    dim3 grid((N + 63) / 64, M / 128, batch);
    if (transB) {
        if (bk64)
            sgemm_kernel<true, 64><<<grid, 128>>>(A, B, C, add, bias, M, N, K, lda, ldb, ldc,
                                                  sA1, sA2, sB1, sB2, sC1, sC2, bdiv, relu, permRows);
        else
            sgemm_kernel<true, 32><<<grid, 128>>>(A, B, C, add, bias, M, N, K, lda, ldb, ldc,
                                                  sA1, sA2, sB1, sB2, sC1, sC2, bdiv, relu, permRows);
    } else {
        if (bk64)
            sgemm_kernel<false, 64><<<grid, 128>>>(A, B, C, add, bias, M, N, K, lda, ldb, ldc,
                                                   sA1, sA2, sB1, sB2, sC1, sC2, bdiv, relu, permRows);
        else
            sgemm_kernel<false, 32><<<grid, 128>>>(A, B, C, add, bias, M, N, K, lda, ldb, ldc,
                                                   sA1, sA2, sB1, sB2, sC1, sC2, bdiv, relu, permRows);
    }
}

extern "C" void kernel_launch(void* const* d_in, const int* in_sizes, int n_in,
                              void* d_out, int out_size)
{
    const float* zL    = (const float*)d_in[0];
    const float* Wq_l  = (const float*)d_in[1];
    const float* Wk_l  = (const float*)d_in[2];
    const float* Wv_l  = (const float*)d_in[3];
    const float* Wo_l  = (const float*)d_in[4];
    const float* gl    = (const float*)d_in[5];
    const float* bl    = (const float*)d_in[6];
    const float* Wq_d  = (const float*)d_in[7];
    const float* Wk_d  = (const float*)d_in[8];
    const float* Wv_d  = (const float*)d_in[9];
    const float* Wo_d  = (const float*)d_in[10];
    const float* gd    = (const float*)d_in[11];
    const float* bd    = (const float*)d_in[12];
    const float* dict  = (const float*)d_in[13];
    const float* biasn = (const float*)d_in[14];
    float* out = (float*)d_out;

    float *p_ln, *p_qkv, *p_wcat, *p_attn, *p_x, *p_sc, *p_res, *p_z, *p_dT, *p_tkv, *p_part;
    int *p_tki;
    cudaGetSymbolAddress((void**)&p_ln,   g_ln);
    cudaGetSymbolAddress((void**)&p_qkv,  g_qkv);
    cudaGetSymbolAddress((void**)&p_wcat, g_wcat);
    cudaGetSymbolAddress((void**)&p_attn, g_attn);
    cudaGetSymbolAddress((void**)&p_x,    g_x);
    cudaGetSymbolAddress((void**)&p_sc,   g_sc);
    cudaGetSymbolAddress((void**)&p_res,  g_res);
    cudaGetSymbolAddress((void**)&p_z,    g_z);
    cudaGetSymbolAddress((void**)&p_dT,   g_dictT);
    cudaGetSymbolAddress((void**)&p_tki,  g_tki);
    cudaGetSymbolAddress((void**)&p_tkv,  g_tkv);
    cudaGetSymbolAddress((void**)&p_part, g_part);

    const long long SQH  = (long long)Ll * Hh;   // 512*768 seq stride (attn buf)
    const long long SQQ  = (long long)Ll * QS;   // 512*2304 seq stride (qkv buf)
    const long long SCB  = (long long)Ll * Ll;   // per-head score size
    const size_t WBYTES  = (size_t)Hh * Hh * sizeof(float);

    // ---------------- Stage A: attention over L (non-causal) ----------------
    ln_kernel<<<ROWS, 256>>>(zL, p_ln, gl, bl, 0);
    cudaMemcpyAsync(p_wcat,             Wq_l, WBYTES, cudaMemcpyDeviceToDevice);
    cudaMemcpyAsync(p_wcat + Hh * Hh,   Wk_l, WBYTES, cudaMemcpyDeviceToDevice);
    cudaMemcpyAsync(p_wcat + 2*Hh*Hh,   Wv_l, WBYTES, cudaMemcpyDeviceToDevice);
    sgemm(true, 1, p_ln, p_wcat, p_qkv, 0, 0, ROWS, QS, Hh, Hh, Hh, QS,
          0,0,0,0,0,0, 1, 1, 0, 0);
    // raw scores (K=96 -> BK=32)
    sgemm(true, 0, p_qkv, p_qkv + 768, p_sc, 0, 0, Ll, Ll, HD, QS, QS, Ll,
          SQQ, HD, SQQ, HD, 8*SCB, SCB, NHEAD, 32*NHEAD, 0, 0);
    softmax512_kernel<<<131072, 128>>>(p_sc);
    // attn = P V  (K=512 -> BK=64)
    sgemm(false, 1, p_sc, p_qkv + 1536, p_attn, 0, 0, Ll, HD, Ll, Ll, QS, Hh,
          8*SCB, SCB, SQQ, HD, SQH, HD, NHEAD, 32*NHEAD, 0, 0);
    // x = zL + attn Wo^T
    sgemm(true, 1, p_attn, Wo_l, p_x, zL, 0, ROWS, Hh, Hh, Hh, Hh, Hh,
          0,0,0,0,0,0, 1, 1, 0, 0);

    // ---------------- Stage B: causal attention over depth D ----------------
    // ln reads p_x with row remap (replaces perm_fwd); outputs (B,L,D) layout
    ln_kernel<<<ROWS, 256>>>(p_x, p_ln, gd, bd, 1);
    cudaMemcpyAsync(p_wcat,             Wq_d, WBYTES, cudaMemcpyDeviceToDevice);
    cudaMemcpyAsync(p_wcat + Hh * Hh,   Wk_d, WBYTES, cudaMemcpyDeviceToDevice);
    cudaMemcpyAsync(p_wcat + 2*Hh*Hh,   Wv_d, WBYTES, cudaMemcpyDeviceToDevice);
    sgemm(true, 1, p_ln, p_wcat, p_qkv, 0, 0, ROWS, QS, Hh, Hh, Hh, QS,
          0,0,0,0,0,0, 1, 1, 0, 0);
    attn2_kernel<<<dim3(2048, NHEAD), 128>>>(p_qkv, p_attn);
    // x = x + attn Wo^T with row-remapped add/C (replaces perm_bwd)
    sgemm(true, 1, p_attn, Wo_d, p_x, p_x, 0, ROWS, Hh, Hh, Hh, Hh, Hh,
          0,0,0,0,0,0, 1, 1, 0, 1);

    // ---------------- SAE head ----------------
    transpose_dict_kernel<<<dim3(128, 24), dim3(32, 8)>>>(dict, p_dT);
    res_kernel<<<43008, 256>>>(p_x, p_res);
    // z_dense = relu(res @ dict + bias)   (K=768 -> BK=64)
    sgemm(false, 1, p_res, dict, p_z, 0, biasn, RES_ROWS, Ff, Hh, Hh, Ff, Ff,
          0,0,0,0,0,0, 1, 1, 1, 0);
    topk_kernel<<<RES_ROWS, 256>>>(p_z, out, p_tki, p_tkv, p_part + 2 * RES_ROWS);
    novel_kernel<<<RES_ROWS, 256>>>(p_dT, p_x, p_tki, p_tkv, out,
                                    p_part, p_part + RES_ROWS);
    loss_kernel<<<1, 256>>>(p_part, p_part + RES_ROWS, p_part + 2 * RES_ROWS, out);
}